// round 13
// baseline (speedup 1.0000x reference)
#include <cuda_runtime.h>
#include <stdint.h>
#include <math.h>

#define TOPK 1000
#define DETS 300
#define NB    4608          // fallback bins via fb>>13 - BASE
#define BASE  125542        // 0x3D4CCCCD >> 13  (0.05f)
#define CAND_CAP 32768
#define SELCAP   6144
#define NCLS  80
#define CLSCAP 1024
#define WCAP  8192
#define SPCAP 8192
#define MAXSLOTS 256
#define FAST_T 0.999f
#define GRID  264
#define NTHR  256

__device__ unsigned          g_barCount;
__device__ volatile unsigned g_barSense;
__device__ unsigned          g_hist1[NB];
__device__ unsigned          g_sel[8];     // [0]=B1 bin  [2]=cand cnt  [4]=work cnt  [5]=sup cnt
__device__ unsigned long long g_cand[CAND_CAP];
__device__ unsigned          g_work[WCAP];
__device__ unsigned          g_supPairs[SPCAP];
__device__ int               g_topIdx[TOPK];
__device__ float             g_topVal[TOPK];
__device__ float             g_bk[TOPK*5];
__device__ float             g_nms[TOPK*5];
__device__ float             g_corn[TOPK*8];
__device__ float             g_aabb[TOPK*4];
__device__ float             g_area[TOPK];
__device__ int               g_clsCnt[NCLS];
__device__ int               g_clsIdx[NCLS*CLSCAP];
__device__ int               g_lab[TOPK];

__device__ __forceinline__ float neginf() { return __int_as_float(0xff800000); }

__device__ __forceinline__ int bin_of(unsigned fb) {
    int b = (int)(fb >> 13) - BASE;
    if (b < 0) b = 0;
    if (b > NB - 1) b = NB - 1;
    return b;
}

__device__ __forceinline__ float sel4(int i, float a, float b, float c, float d) {
    return (i == 0) ? a : (i == 1) ? b : (i == 2) ? c : d;
}

// sense-reversing software grid barrier (all blocks co-resident: GRID <= 2*#SM, 2 CTAs/SM fit)
__device__ __forceinline__ void gbar(unsigned* shSense) {
    __syncthreads();
    if (threadIdx.x == 0) {
        unsigned s = *shSense ^ 1u;
        *shSense = s;
        __threadfence();
        unsigned arrived = atomicAdd(&g_barCount, 1u) + 1u;
        if (arrived == (unsigned)gridDim.x) {
            atomicExch(&g_barCount, 0u);
            __threadfence();
            g_barSense = s;
        } else {
            while (g_barSense != s) __nanosleep(32);
        }
        __threadfence();
    }
    __syncthreads();
}

// ---------------------------------------------------------------- warp-cooperative exact clip (bitwise == scalar reference replica)
__device__ __forceinline__ float warp_inter_area(int bi, int bj, int lane) {
    const unsigned FULL = 0xffffffffu;
    const float eps = 1e-6f;
    const float ONEPE = 1.000001f;
    const float* A  = &g_nms[bi*5];
    const float* B  = &g_nms[bj*5];
    const float* cA = &g_corn[bi*8];
    const float* cB = &g_corn[bj*8];
    float ax0=cA[0], ay0=cA[1], ax1=cA[2], ay1=cA[3], ax2=cA[4], ay2=cA[5], ax3=cA[6], ay3=cA[7];
    float bx0=cB[0], by0=cB[1], bx1=cB[2], by1=cB[3], bx2=cB[4], by2=cB[5], bx3=cB[6], by3=cB[7];
    float Acx=A[0], Acy=A[1], Aw=A[2], Ah=A[3], Aa=A[4];
    float Bcx=B[0], Bcy=B[1], Bw=B[2], Bh=B[3], Ba=B[4];

    float dAx0=__fsub_rn(ax1,ax0), dAy0=__fsub_rn(ay1,ay0);
    float dAx1=__fsub_rn(ax2,ax1), dAy1=__fsub_rn(ay2,ay1);
    float dAx2=__fsub_rn(ax3,ax2), dAy2=__fsub_rn(ay3,ay2);
    float dAx3=__fsub_rn(ax0,ax3), dAy3=__fsub_rn(ay0,ay3);
    float dBx0=__fsub_rn(bx1,bx0), dBy0=__fsub_rn(by1,by0);
    float dBx1=__fsub_rn(bx2,bx1), dBy1=__fsub_rn(by2,by1);
    float dBx2=__fsub_rn(bx3,bx2), dBy2=__fsub_rn(by3,by2);
    float dBx3=__fsub_rn(bx0,bx3), dBy3=__fsub_rn(by0,by3);

    float px = 0.0f, py = 0.0f;
    bool  vl = false;
    if (lane < 8) {
        int  c4  = lane & 3;
        bool isA = lane < 4;
        float ptx = isA ? sel4(c4, ax0,ax1,ax2,ax3) : sel4(c4, bx0,bx1,bx2,bx3);
        float pty = isA ? sel4(c4, ay0,ay1,ay2,ay3) : sel4(c4, by0,by1,by2,by3);
        float tcx = isA ? Bcx : Acx;
        float tcy = isA ? Bcy : Acy;
        float tw  = isA ? Bw  : Aw;
        float th  = isA ? Bh  : Ah;
        float ta  = isA ? Ba  : Aa;
        float cc = cosf(ta), ss = sinf(ta);
        float rx = __fsub_rn(ptx, tcx), ry = __fsub_rn(pty, tcy);
        float xr = __fadd_rn(__fmul_rn(rx, cc), __fmul_rn(ry, ss));
        float yr = __fadd_rn(__fmul_rn(-rx, ss), __fmul_rn(ry, cc));
        float lw = __fadd_rn(__fmul_rn(tw, 0.5f), eps);
        float lh = __fadd_rn(__fmul_rn(th, 0.5f), eps);
        vl = (fabsf(xr) <= lw) && (fabsf(yr) <= lh);
        px = ptx; py = pty;
    } else if (lane < 24) {
        int ii = (lane - 8) >> 2, jj = (lane - 8) & 3;
        float axi = sel4(ii, ax0,ax1,ax2,ax3), ayi = sel4(ii, ay0,ay1,ay2,ay3);
        float dxi = sel4(ii, dAx0,dAx1,dAx2,dAx3), dyi = sel4(ii, dAy0,dAy1,dAy2,dAy3);
        float bxj = sel4(jj, bx0,bx1,bx2,bx3), byj = sel4(jj, by0,by1,by2,by3);
        float exj = sel4(jj, dBx0,dBx1,dBx2,dBx3), eyj = sel4(jj, dBy0,dBy1,dBy2,dBy3);
        float rx  = __fsub_rn(bxj, axi), ry = __fsub_rn(byj, ayi);
        float den = __fsub_rn(__fmul_rn(dxi, eyj), __fmul_rn(dyi, exj));
        float ad  = fabsf(den);
        float dens = (ad < 1e-9f) ? 1.0f : den;
        float t = __fsub_rn(__fmul_rn(rx, eyj), __fmul_rn(ry, exj)) / dens;
        float u = __fsub_rn(__fmul_rn(rx, dyi), __fmul_rn(ry, dxi)) / dens;
        vl = (ad > 1e-9f) && (t >= -eps) && (t <= ONEPE) && (u >= -eps) && (u <= ONEPE);
        px = __fadd_rn(axi, __fmul_rn(t, dxi));
        py = __fadd_rn(ayi, __fmul_rn(t, dyi));
    }

    unsigned bal = __ballot_sync(FULL, vl) & 0x00FFFFFFu;
    int cnt = __popc(bal);

    float f = vl ? 1.0f : 0.0f;
    float contx = __fmul_rn(px, f);
    float conty = __fmul_rn(py, f);
    float sx = 0.0f, sy = 0.0f;
#pragma unroll
    for (int m = 0; m < 24; m++) {
        float vx = __shfl_sync(FULL, contx, m);
        float vy = __shfl_sync(FULL, conty, m);
        sx = __fadd_rn(sx, vx);
        sy = __fadd_rn(sy, vy);
    }
    int cm = cnt > 1 ? cnt : 1;
    float cenx = sx / (float)cm, ceny = sy / (float)cm;

    int am = bal ? (__ffs(bal) - 1) : 0;
    float anx  = __shfl_sync(FULL, px, am);
    float anyy = __shfl_sync(FULL, py, am);

    float qx = vl ? px : anx;
    float qy = vl ? py : anyy;
    float ang = atan2f(__fsub_rn(qy, ceny), __fsub_rn(qx, cenx));

    int rank = (lane < 24) ? 0 : (100 + lane);
#pragma unroll
    for (int m = 0; m < 24; m++) {
        float am_ = __shfl_sync(FULL, ang, m);
        if (lane < 24 && m != lane) {
            bool less = (am_ < ang) || (am_ == ang && m < lane);
            rank += less ? 1 : 0;
        }
    }

    float X = 0.0f, Y = 0.0f;
#pragma unroll
    for (int m = 0; m < 24; m++) {
        int   rm = __shfl_sync(FULL, rank, m);
        float xm = __shfl_sync(FULL, qx, m);
        float ym = __shfl_sync(FULL, qy, m);
        if (rm == lane) { X = xm; Y = ym; }
    }
    int nxt = (lane == 23) ? 0 : lane + 1;
    float Xn = __shfl_sync(FULL, X, nxt);
    float Yn = __shfl_sync(FULL, Y, nxt);
    float term = __fsub_rn(__fmul_rn(X, Yn), __fmul_rn(Xn, Y));

    float ssum = 0.0f;
#pragma unroll
    for (int m = 0; m < 24; m++) {
        float tv = __shfl_sync(FULL, term, m);
        ssum = __fadd_rn(ssum, tv);
    }
    float area = __fmul_rn(0.5f, fabsf(ssum));
    return (cnt >= 3) ? area : 0.0f;
}

// ---------------------------------------------------------------- ONE persistent kernel, software grid barriers
extern __shared__ unsigned char dynbuf[];   // 49152 B

__global__ void __launch_bounds__(NTHR, 2)
k_all(const float* __restrict__ boxes, const float4* __restrict__ sc4,
      const int* __restrict__ labels, float* __restrict__ out, int n4) {
    __shared__ unsigned shSense;
    __shared__ unsigned shC;
    __shared__ int shSkip;
    int tid = threadIdx.x;
    int bid = blockIdx.x;
    if (tid == 0) shSense = 0u;
    __syncthreads();

    // ---------------- P1: default-init + fast compact (s > FAST_T), MLP=8 ----------------
    {
        int gid = bid * NTHR + tid;
        int S   = GRID * NTHR;
        for (int i = gid; i < TOPK; i += S) {
            g_topIdx[i] = -1;
            g_topVal[i] = neginf();
        }
        for (int p = gid; p < n4; p += 8 * S) {
            float4 vv[8];
            int    pp[8];
#pragma unroll
            for (int q = 0; q < 8; q++) {
                pp[q] = p + q * S;
                vv[q] = (pp[q] < n4) ? sc4[pp[q]] : make_float4(0,0,0,0);
            }
#pragma unroll
            for (int q = 0; q < 8; q++) {
                float vs[4] = { vv[q].x, vv[q].y, vv[q].z, vv[q].w };
#pragma unroll
                for (int l = 0; l < 4; l++) {
                    float s = vs[l];
                    if (s > FAST_T) {
                        unsigned pos = atomicAdd(&g_sel[2], 1u);
                        if (pos < CAND_CAP) {
                            unsigned idx = (unsigned)(pp[q] * 4 + l);
                            g_cand[pos] = ((unsigned long long)__float_as_uint(s) << 32) |
                                          (unsigned long long)(0xFFFFFFFFu - idx);
                        }
                    }
                }
            }
        }
    }
    gbar(&shSense);                                            // B1

    // ---------------- P2: skip decision (+ fallback path) ----------------
    if (tid == 0) {
        unsigned ct = g_sel[2];
        shSkip = (ct >= TOPK && ct <= CAND_CAP) ? 1 : 0;
    }
    __syncthreads();
    int skip = shSkip;                                         // grid-uniform
    if (!skip) {
        // ---- fallback (correct, barrier-balanced; not hit on this data) ----
        unsigned* h = (unsigned*)dynbuf;
        for (int k = tid; k < NB; k += NTHR) h[k] = 0u;
        __syncthreads();
        for (int p = bid * NTHR + tid; p < n4; p += GRID * NTHR) {
            float4 v = sc4[p];
            float vs[4] = { v.x, v.y, v.z, v.w };
#pragma unroll
            for (int l = 0; l < 4; l++)
                if (vs[l] > 0.05f) atomicAdd(&h[bin_of(__float_as_uint(vs[l]))], 1u);
        }
        __syncthreads();
        for (int k = tid; k < NB; k += NTHR) {
            unsigned v = h[k];
            if (v) atomicAdd(&g_hist1[k], v);
        }
        gbar(&shSense);                                        // Bf1
        if (bid == 0 && tid == 0) {
            unsigned cum = 0; int B1 = -1;
            for (int b = NB - 1; b >= 0; b--) {
                unsigned c = g_hist1[b];
                if (cum + c >= TOPK) { B1 = b; break; }
                cum += c;
            }
            if (B1 < 0) B1 = 0;
            g_sel[0] = (unsigned)B1;
            g_sel[2] = 0u;
        }
        gbar(&shSense);                                        // Bf2
        {
            unsigned B1 = g_sel[0];
            for (int p = bid * NTHR + tid; p < n4; p += GRID * NTHR) {
                float4 v = sc4[p];
                float vs[4] = { v.x, v.y, v.z, v.w };
#pragma unroll
                for (int l = 0; l < 4; l++) {
                    float s = vs[l];
                    if (s > 0.05f) {
                        unsigned fb = __float_as_uint(s);
                        if (bin_of(fb) >= (int)B1) {
                            unsigned pos = atomicAdd(&g_sel[2], 1u);
                            if (pos < CAND_CAP) {
                                unsigned idx = (unsigned)(p * 4 + l);
                                g_cand[pos] = ((unsigned long long)fb << 32) |
                                              (unsigned long long)(0xFFFFFFFFu - idx);
                            }
                        }
                    }
                }
            }
        }
        gbar(&shSense);                                        // Bf3
    }
    gbar(&shSense);                                            // B2 (select inputs ready)

    // ---------------- P3: select (16-lane cooperative rank, uniform iterations) ----------------
    {
        if (tid == 0) shC = g_sel[2];
        __syncthreads();
        unsigned C = shC;
        if (C > CAND_CAP) C = CAND_CAP;
        unsigned long long* sk = (unsigned long long*)dynbuf;  // 49152 B = SELCAP u64
        bool small = (C <= SELCAP);
        const unsigned long long* base;
        if (small) {
            for (unsigned k = (unsigned)tid; k < C; k += NTHR) sk[k] = g_cand[k];
            base = sk;
        } else {
            base = g_cand;
        }
        __syncthreads();
        unsigned lane  = (unsigned)tid & 15u;
        unsigned gidx  = (unsigned)(bid * NTHR + tid) >> 4;
        unsigned cstr  = (unsigned)(GRID * NTHR) >> 4;
        unsigned nIter = (C + cstr - 1) / cstr;                // uniform across grid
        for (unsigned it = 0; it < nIter; it++) {
            unsigned c = gidx + it * cstr;
            bool act = (c < C);
            unsigned long long key = act ? base[c] : 0ULL;
            unsigned rank = 0;
            unsigned k = lane;
            for (; k + 48 < C; k += 64) {
                unsigned long long a0 = base[k], a1 = base[k+16], a2 = base[k+32], a3 = base[k+48];
                rank += (a0 > key) + (a1 > key) + (a2 > key) + (a3 > key);
            }
            for (; k < C; k += 16) rank += (base[k] > key) ? 1u : 0u;
            rank += __shfl_down_sync(0xffffffffu, rank, 8, 16);
            rank += __shfl_down_sync(0xffffffffu, rank, 4, 16);
            rank += __shfl_down_sync(0xffffffffu, rank, 2, 16);
            rank += __shfl_down_sync(0xffffffffu, rank, 1, 16);
            if (act && lane == 0 && rank < TOPK) {
                g_topIdx[rank] = (int)(0xFFFFFFFFu - (unsigned)(key & 0xFFFFFFFFull));
                g_topVal[rank] = __uint_as_float((unsigned)(key >> 32));
            }
        }
    }
    gbar(&shSense);                                            // B3

    // ---------------- P4: prep (spread over grid) ----------------
    for (int i = bid * NTHR + tid; i < TOPK; i += GRID * NTHR) {
        int idx = g_topIdx[i];
        if (idx < 0) { g_lab[i] = -1 - NCLS; g_area[i] = 0.0f; continue; }
        float cx = boxes[idx*5+0], cy = boxes[idx*5+1];
        float w  = boxes[idx*5+2], h  = boxes[idx*5+3];
        float a  = boxes[idx*5+4];
        g_bk[i*5+0]=cx; g_bk[i*5+1]=cy; g_bk[i*5+2]=w; g_bk[i*5+3]=h; g_bk[i*5+4]=a;
        int lab = labels[idx];
        g_lab[i] = lab;
        float off = __fmul_rn((float)lab, 10000.0f);
        float cxo = __fadd_rn(cx, off);
        float cyo = __fadd_rn(cy, off);
        g_nms[i*5+0]=cxo; g_nms[i*5+1]=cyo; g_nms[i*5+2]=w; g_nms[i*5+3]=h; g_nms[i*5+4]=a;
        g_area[i] = __fmul_rn(w, h);
        float c = cosf(a), s = sinf(a);
        float dx = __fmul_rn(w, 0.5f), dy = __fmul_rn(h, 0.5f);
        float ox[4] = { dx, -dx, -dx,  dx };
        float oy[4] = { dy,  dy, -dy, -dy };
        float mnx =  3.4e38f, mxx = -3.4e38f, mny = 3.4e38f, mxy = -3.4e38f;
#pragma unroll
        for (int j = 0; j < 4; j++) {
            float x = __fsub_rn(__fadd_rn(cxo, __fmul_rn(ox[j], c)), __fmul_rn(oy[j], s));
            float y = __fadd_rn(__fadd_rn(cyo, __fmul_rn(ox[j], s)), __fmul_rn(oy[j], c));
            g_corn[i*8 + 2*j]     = x;
            g_corn[i*8 + 2*j + 1] = y;
            mnx = fminf(mnx, x); mxx = fmaxf(mxx, x);
            mny = fminf(mny, y); mxy = fmaxf(mxy, y);
        }
        g_aabb[i*4+0]=mnx; g_aabb[i*4+1]=mxx; g_aabb[i*4+2]=mny; g_aabb[i*4+3]=mxy;
        if (lab >= 0 && lab < NCLS) {
            int pos = atomicAdd(&g_clsCnt[lab], 1);
            if (pos < CLSCAP) g_clsIdx[lab*CLSCAP + pos] = i;
        }
    }
    gbar(&shSense);                                            // B4

    // ---------------- P5: AABB sieve (classes spread over blocks) ----------------
    for (int c = bid; c < NCLS; c += GRID) {
        int n = g_clsCnt[c];
        if (n > CLSCAP) n = CLSCAP;
        if (n < 2) continue;
        const int* cl = &g_clsIdx[c*CLSCAP];
        for (int t = tid; t < n*n; t += NTHR) {
            int i_ = t / n, j_ = t - i_ * n;
            if (i_ >= j_) continue;
            int a = cl[i_], b = cl[j_];
            if (a > b) { int tmp = a; a = b; b = tmp; }
            const float M = 1.0f;
            if (g_aabb[a*4+0] > g_aabb[b*4+1] + M || g_aabb[b*4+0] > g_aabb[a*4+1] + M ||
                g_aabb[a*4+2] > g_aabb[b*4+3] + M || g_aabb[b*4+2] > g_aabb[a*4+3] + M) continue;
            unsigned pos = atomicAdd(&g_sel[4], 1u);
            if (pos < WCAP) g_work[pos] = ((unsigned)a << 16) | (unsigned)b;
        }
    }
    gbar(&shSense);                                            // B5

    // ---------------- P6: warp-cooperative clips (warp-uniform loop) ----------------
    {
        int lane = tid & 31;
        unsigned W = g_sel[4];
        if (W > WCAP) W = WCAP;
        unsigned gw = (unsigned)(bid * NTHR + tid) >> 5;
        unsigned nw = (unsigned)(GRID * NTHR) >> 5;
        for (unsigned c = gw; c < W; c += nw) {
            unsigned e = g_work[c];
            int i = (int)(e >> 16), j = (int)(e & 0xFFFFu);
            float inter = warp_inter_area(i, j, lane);
            if (lane == 0) {
                float S   = __fadd_rn(__fsub_rn(__fadd_rn(g_area[i], g_area[j]), inter), 1e-6f);
                float iou = inter / S;
                if (iou > 0.5f) {
                    unsigned pos = atomicAdd(&g_sel[5], 1u);
                    if (pos < SPCAP) g_supPairs[pos] = e;
                }
            }
        }
    }
    gbar(&shSense);                                            // B6

    // ---------------- P7: block 0 — slot-compacted NMS + output + full self-clean ----------------
    if (bid != 0) return;
    {
        __shared__ unsigned keepW[32];
        __shared__ unsigned raW[32];
        __shared__ unsigned wbase[32];
        __shared__ int lst[DETS];
        __shared__ int kcnt;
        __shared__ int nslots;
        unsigned* mask = (unsigned*)dynbuf;                    // 32KB within dynbuf
        if (tid < 32) { keepW[tid] = 0u; raW[tid] = 0u; }
        __syncthreads();
        for (int i = tid; i < TOPK; i += NTHR)
            if (g_topVal[i] > neginf()) atomicOr(&keepW[i >> 5], 1u << (i & 31));
        unsigned P = g_sel[5];
        if (P > SPCAP) P = SPCAP;
        for (unsigned p = (unsigned)tid; p < P; p += NTHR) {
            unsigned i = g_supPairs[p] >> 16;
            atomicOr(&raW[i >> 5], 1u << (i & 31));
        }
        __syncthreads();
        if (tid < 32) {
            unsigned cnt = __popc(raW[tid]);
            unsigned ex = cnt;
#pragma unroll
            for (int d = 1; d < 32; d <<= 1) {
                unsigned v = __shfl_up_sync(0xffffffffu, ex, d);
                if (tid >= d) ex += v;
            }
            wbase[tid] = ex - cnt;
            if (tid == 31) nslots = (int)ex;
        }
        __syncthreads();
        int NS = nslots;
        if (NS <= MAXSLOTS) {
            for (int k = tid; k < NS * 32; k += NTHR) mask[k] = 0u;
            __syncthreads();
            for (unsigned p = (unsigned)tid; p < P; p += NTHR) {
                unsigned e = g_supPairs[p];
                unsigned i = e >> 16, j = e & 0xFFFFu;
                unsigned w = i >> 5, b = i & 31;
                unsigned slot = wbase[w] + __popc(raW[w] & ((1u << b) - 1u));
                atomicOr(&mask[slot * 32 + (j >> 5)], 1u << (j & 31));
            }
            __syncthreads();
            if (tid < 32) {
                int s = 0;
                for (int w = 0; w < 32; w++) {
                    unsigned rb = raW[w];
                    while (rb) {
                        int b = __ffs(rb) - 1;
                        rb &= rb - 1;
                        bool kept = (keepW[w] >> b) & 1u;
                        if (kept) keepW[tid] &= ~mask[s * 32 + tid];
                        s++;
                        __syncwarp();
                    }
                }
            }
        } else if (tid == 0) {
            for (int w = 0; w < 32; w++) {
                unsigned rb = raW[w];
                while (rb) {
                    int b = __ffs(rb) - 1;
                    rb &= rb - 1;
                    int i = w * 32 + b;
                    if (keepW[w] & (1u << b)) {
                        for (unsigned p = 0; p < P; p++) {
                            unsigned e = g_supPairs[p];
                            if ((int)(e >> 16) == i) {
                                int j = (int)(e & 0xFFFFu);
                                keepW[j >> 5] &= ~(1u << (j & 31));
                            }
                        }
                    }
                }
            }
        }
        __syncthreads();
        if (tid == 0) {
            int p = 0;
            for (int w = 0; w < 32 && p < DETS; w++) {
                unsigned m = keepW[w];
                while (m && p < DETS) {
                    int b = __ffs(m) - 1;
                    m &= m - 1;
                    lst[p++] = w * 32 + b;
                }
            }
            kcnt = p;
        }
        __syncthreads();
        for (int r = tid; r < DETS; r += NTHR) {
            if (r < kcnt) {
                int i = lst[r];
#pragma unroll
                for (int k = 0; k < 5; k++) out[r*5+k] = g_bk[i*5+k];
                out[DETS*5 + r] = (float)g_lab[i];
                out[DETS*6 + r] = g_topVal[i];
            } else {
#pragma unroll
                for (int k = 0; k < 5; k++) out[r*5+k] = 0.0f;
                out[DETS*5 + r] = -1.0f;
                out[DETS*6 + r] = 0.0f;
            }
        }
        // full self-clean for next replay (all blocks past final barrier)
        for (int k = tid; k < 8; k += NTHR) g_sel[k] = 0u;
        for (int c = tid; c < NCLS; c += NTHR) g_clsCnt[c] = 0;
        if (!skip) for (int k = tid; k < NB; k += NTHR) g_hist1[k] = 0u;
        __syncthreads();
        if (tid == 0) { g_barCount = 0u; g_barSense = 0u; }
    }
}

// ---------------------------------------------------------------- launcher: ONE kernel
extern "C" void kernel_launch(void* const* d_in, const int* in_sizes, int n_in,
                              void* d_out, int out_size) {
    const float* boxes  = (const float*)d_in[0];
    const float* scores = (const float*)d_in[1];
    const int*   labels = (const int*)d_in[2];
    int n = in_sizes[1];
    int n4 = n / 4;

    static const int DYN = SELCAP * 8;   // 49152 B
    cudaFuncSetAttribute(k_all, cudaFuncAttributeMaxDynamicSharedMemorySize, DYN);
    k_all<<<GRID, NTHR, DYN>>>(boxes, (const float4*)scores, labels, (float*)d_out, n4);
}

// round 14
// speedup vs baseline: 1.1411x; 1.1411x over previous
#include <cuda_runtime.h>
#include <stdint.h>
#include <math.h>

#define TOPK 1000
#define DETS 300
#define NB    4608          // fallback bins via fb>>13 - BASE
#define BASE  125542        // 0x3D4CCCCD >> 13  (0.05f)
#define CAND_CAP 32768
#define SELCAP   6144
#define NCLS  80
#define CLSCAP 1024
#define PAIR_SH 2048
#define SPCAP 8192
#define MAXSLOTS 256
#define FAST_T 0.999f
#define GRID  132
#define NTHR  256

__device__ unsigned          g_barCount;
__device__ volatile unsigned g_barSense;
__device__ unsigned          g_hist1[NB];
__device__ unsigned          g_sel[8];     // [0]=B1 bin  [2]=cand cnt  [5]=sup cnt
__device__ unsigned long long g_cand[CAND_CAP];
__device__ unsigned          g_supPairs[SPCAP];
__device__ int               g_topIdx[TOPK];
__device__ float             g_topVal[TOPK];
__device__ float             g_bk[TOPK*5];
__device__ float             g_nms[TOPK*5];
__device__ float             g_corn[TOPK*8];
__device__ float             g_aabb[TOPK*4];
__device__ float             g_area[TOPK];
__device__ int               g_clsCnt[NCLS];
__device__ int               g_clsIdx[NCLS*CLSCAP];
__device__ int               g_lab[TOPK];

__device__ __forceinline__ float neginf() { return __int_as_float(0xff800000); }

__device__ __forceinline__ int bin_of(unsigned fb) {
    int b = (int)(fb >> 13) - BASE;
    if (b < 0) b = 0;
    if (b > NB - 1) b = NB - 1;
    return b;
}

__device__ __forceinline__ float sel4(int i, float a, float b, float c, float d) {
    return (i == 0) ? a : (i == 1) ? b : (i == 2) ? c : d;
}

// sense-reversing software grid barrier (all blocks co-resident: GRID <= #SM)
__device__ __forceinline__ void gbar(unsigned* shSense) {
    __syncthreads();
    if (threadIdx.x == 0) {
        unsigned s = *shSense ^ 1u;
        *shSense = s;
        __threadfence();
        unsigned arrived = atomicAdd(&g_barCount, 1u) + 1u;
        if (arrived == (unsigned)gridDim.x) {
            atomicExch(&g_barCount, 0u);
            __threadfence();
            g_barSense = s;
        } else {
            while (g_barSense != s) __nanosleep(32);
        }
        __threadfence();
    }
    __syncthreads();
}

// ---------------------------------------------------------------- warp-cooperative exact clip (bitwise == scalar reference replica)
__device__ __forceinline__ float warp_inter_area(int bi, int bj, int lane) {
    const unsigned FULL = 0xffffffffu;
    const float eps = 1e-6f;
    const float ONEPE = 1.000001f;
    const float* A  = &g_nms[bi*5];
    const float* B  = &g_nms[bj*5];
    const float* cA = &g_corn[bi*8];
    const float* cB = &g_corn[bj*8];
    float ax0=cA[0], ay0=cA[1], ax1=cA[2], ay1=cA[3], ax2=cA[4], ay2=cA[5], ax3=cA[6], ay3=cA[7];
    float bx0=cB[0], by0=cB[1], bx1=cB[2], by1=cB[3], bx2=cB[4], by2=cB[5], bx3=cB[6], by3=cB[7];
    float Acx=A[0], Acy=A[1], Aw=A[2], Ah=A[3], Aa=A[4];
    float Bcx=B[0], Bcy=B[1], Bw=B[2], Bh=B[3], Ba=B[4];

    float dAx0=__fsub_rn(ax1,ax0), dAy0=__fsub_rn(ay1,ay0);
    float dAx1=__fsub_rn(ax2,ax1), dAy1=__fsub_rn(ay2,ay1);
    float dAx2=__fsub_rn(ax3,ax2), dAy2=__fsub_rn(ay3,ay2);
    float dAx3=__fsub_rn(ax0,ax3), dAy3=__fsub_rn(ay0,ay3);
    float dBx0=__fsub_rn(bx1,bx0), dBy0=__fsub_rn(by1,by0);
    float dBx1=__fsub_rn(bx2,bx1), dBy1=__fsub_rn(by2,by1);
    float dBx2=__fsub_rn(bx3,bx2), dBy2=__fsub_rn(by3,by2);
    float dBx3=__fsub_rn(bx0,bx3), dBy3=__fsub_rn(by0,by3);

    float px = 0.0f, py = 0.0f;
    bool  vl = false;
    if (lane < 8) {
        int  c4  = lane & 3;
        bool isA = lane < 4;
        float ptx = isA ? sel4(c4, ax0,ax1,ax2,ax3) : sel4(c4, bx0,bx1,bx2,bx3);
        float pty = isA ? sel4(c4, ay0,ay1,ay2,ay3) : sel4(c4, by0,by1,by2,by3);
        float tcx = isA ? Bcx : Acx;
        float tcy = isA ? Bcy : Acy;
        float tw  = isA ? Bw  : Aw;
        float th  = isA ? Bh  : Ah;
        float ta  = isA ? Ba  : Aa;
        float cc = cosf(ta), ss = sinf(ta);
        float rx = __fsub_rn(ptx, tcx), ry = __fsub_rn(pty, tcy);
        float xr = __fadd_rn(__fmul_rn(rx, cc), __fmul_rn(ry, ss));
        float yr = __fadd_rn(__fmul_rn(-rx, ss), __fmul_rn(ry, cc));
        float lw = __fadd_rn(__fmul_rn(tw, 0.5f), eps);
        float lh = __fadd_rn(__fmul_rn(th, 0.5f), eps);
        vl = (fabsf(xr) <= lw) && (fabsf(yr) <= lh);
        px = ptx; py = pty;
    } else if (lane < 24) {
        int ii = (lane - 8) >> 2, jj = (lane - 8) & 3;
        float axi = sel4(ii, ax0,ax1,ax2,ax3), ayi = sel4(ii, ay0,ay1,ay2,ay3);
        float dxi = sel4(ii, dAx0,dAx1,dAx2,dAx3), dyi = sel4(ii, dAy0,dAy1,dAy2,dAy3);
        float bxj = sel4(jj, bx0,bx1,bx2,bx3), byj = sel4(jj, by0,by1,by2,by3);
        float exj = sel4(jj, dBx0,dBx1,dBx2,dBx3), eyj = sel4(jj, dBy0,dBy1,dBy2,dBy3);
        float rx  = __fsub_rn(bxj, axi), ry = __fsub_rn(byj, ayi);
        float den = __fsub_rn(__fmul_rn(dxi, eyj), __fmul_rn(dyi, exj));
        float ad  = fabsf(den);
        float dens = (ad < 1e-9f) ? 1.0f : den;
        float t = __fsub_rn(__fmul_rn(rx, eyj), __fmul_rn(ry, exj)) / dens;
        float u = __fsub_rn(__fmul_rn(rx, dyi), __fmul_rn(ry, dxi)) / dens;
        vl = (ad > 1e-9f) && (t >= -eps) && (t <= ONEPE) && (u >= -eps) && (u <= ONEPE);
        px = __fadd_rn(axi, __fmul_rn(t, dxi));
        py = __fadd_rn(ayi, __fmul_rn(t, dyi));
    }

    unsigned bal = __ballot_sync(FULL, vl) & 0x00FFFFFFu;
    int cnt = __popc(bal);

    float f = vl ? 1.0f : 0.0f;
    float contx = __fmul_rn(px, f);
    float conty = __fmul_rn(py, f);
    float sx = 0.0f, sy = 0.0f;
#pragma unroll
    for (int m = 0; m < 24; m++) {
        float vx = __shfl_sync(FULL, contx, m);
        float vy = __shfl_sync(FULL, conty, m);
        sx = __fadd_rn(sx, vx);
        sy = __fadd_rn(sy, vy);
    }
    int cm = cnt > 1 ? cnt : 1;
    float cenx = sx / (float)cm, ceny = sy / (float)cm;

    int am = bal ? (__ffs(bal) - 1) : 0;
    float anx  = __shfl_sync(FULL, px, am);
    float anyy = __shfl_sync(FULL, py, am);

    float qx = vl ? px : anx;
    float qy = vl ? py : anyy;
    float ang = atan2f(__fsub_rn(qy, ceny), __fsub_rn(qx, cenx));

    int rank = (lane < 24) ? 0 : (100 + lane);
#pragma unroll
    for (int m = 0; m < 24; m++) {
        float am_ = __shfl_sync(FULL, ang, m);
        if (lane < 24 && m != lane) {
            bool less = (am_ < ang) || (am_ == ang && m < lane);
            rank += less ? 1 : 0;
        }
    }

    float X = 0.0f, Y = 0.0f;
#pragma unroll
    for (int m = 0; m < 24; m++) {
        int   rm = __shfl_sync(FULL, rank, m);
        float xm = __shfl_sync(FULL, qx, m);
        float ym = __shfl_sync(FULL, qy, m);
        if (rm == lane) { X = xm; Y = ym; }
    }
    int nxt = (lane == 23) ? 0 : lane + 1;
    float Xn = __shfl_sync(FULL, X, nxt);
    float Yn = __shfl_sync(FULL, Y, nxt);
    float term = __fsub_rn(__fmul_rn(X, Yn), __fmul_rn(Xn, Y));

    float ssum = 0.0f;
#pragma unroll
    for (int m = 0; m < 24; m++) {
        float tv = __shfl_sync(FULL, term, m);
        ssum = __fadd_rn(ssum, tv);
    }
    float area = __fmul_rn(0.5f, fabsf(ssum));
    return (cnt >= 3) ? area : 0.0f;
}

// prep one selected row (rank r, source idx): gather + offset + corners + AABB + class insert
__device__ __forceinline__ void prep_row(int r, int idx, const float* __restrict__ boxes,
                                         const int* __restrict__ labels) {
    float cx = boxes[idx*5+0], cy = boxes[idx*5+1];
    float w  = boxes[idx*5+2], h  = boxes[idx*5+3];
    float a  = boxes[idx*5+4];
    g_bk[r*5+0]=cx; g_bk[r*5+1]=cy; g_bk[r*5+2]=w; g_bk[r*5+3]=h; g_bk[r*5+4]=a;
    int lab = labels[idx];
    g_lab[r] = lab;
    float off = __fmul_rn((float)lab, 10000.0f);
    float cxo = __fadd_rn(cx, off);
    float cyo = __fadd_rn(cy, off);
    g_nms[r*5+0]=cxo; g_nms[r*5+1]=cyo; g_nms[r*5+2]=w; g_nms[r*5+3]=h; g_nms[r*5+4]=a;
    g_area[r] = __fmul_rn(w, h);
    float c = cosf(a), s = sinf(a);
    float dx = __fmul_rn(w, 0.5f), dy = __fmul_rn(h, 0.5f);
    float ox[4] = { dx, -dx, -dx,  dx };
    float oy[4] = { dy,  dy, -dy, -dy };
    float mnx =  3.4e38f, mxx = -3.4e38f, mny = 3.4e38f, mxy = -3.4e38f;
#pragma unroll
    for (int j = 0; j < 4; j++) {
        float x = __fsub_rn(__fadd_rn(cxo, __fmul_rn(ox[j], c)), __fmul_rn(oy[j], s));
        float y = __fadd_rn(__fadd_rn(cyo, __fmul_rn(ox[j], s)), __fmul_rn(oy[j], c));
        g_corn[r*8 + 2*j]     = x;
        g_corn[r*8 + 2*j + 1] = y;
        mnx = fminf(mnx, x); mxx = fmaxf(mxx, x);
        mny = fminf(mny, y); mxy = fmaxf(mxy, y);
    }
    g_aabb[r*4+0]=mnx; g_aabb[r*4+1]=mxx; g_aabb[r*4+2]=mny; g_aabb[r*4+3]=mxy;
    if (lab >= 0 && lab < NCLS) {
        int pos = atomicAdd(&g_clsCnt[lab], 1);
        if (pos < CLSCAP) g_clsIdx[lab*CLSCAP + pos] = r;
    }
}

// ---------------------------------------------------------------- ONE persistent kernel, 4 grid barriers (fast path)
extern __shared__ unsigned char dynbuf[];   // 49152 B

__global__ void __launch_bounds__(NTHR, 2)
k_all(const float* __restrict__ boxes, const float4* __restrict__ sc4,
      const int* __restrict__ labels, float* __restrict__ out, int n4) {
    __shared__ unsigned shSense;
    __shared__ unsigned shC;
    __shared__ int shSkip;
    int tid = threadIdx.x;
    int bid = blockIdx.x;
    if (tid == 0) shSense = 0u;
    __syncthreads();

    // ---------------- P1: default-init + fast compact (s > FAST_T), MLP=8 ----------------
    {
        int gid = bid * NTHR + tid;
        int S   = GRID * NTHR;
        for (int i = gid; i < TOPK; i += S) {
            g_topIdx[i] = -1;
            g_topVal[i] = neginf();
        }
        for (int p = gid; p < n4; p += 8 * S) {
            float4 vv[8];
            int    pp[8];
#pragma unroll
            for (int q = 0; q < 8; q++) {
                pp[q] = p + q * S;
                vv[q] = (pp[q] < n4) ? sc4[pp[q]] : make_float4(0,0,0,0);
            }
#pragma unroll
            for (int q = 0; q < 8; q++) {
                float vs[4] = { vv[q].x, vv[q].y, vv[q].z, vv[q].w };
#pragma unroll
                for (int l = 0; l < 4; l++) {
                    float s = vs[l];
                    if (s > FAST_T) {
                        unsigned pos = atomicAdd(&g_sel[2], 1u);
                        if (pos < CAND_CAP) {
                            unsigned idx = (unsigned)(pp[q] * 4 + l);
                            g_cand[pos] = ((unsigned long long)__float_as_uint(s) << 32) |
                                          (unsigned long long)(0xFFFFFFFFu - idx);
                        }
                    }
                }
            }
        }
    }
    gbar(&shSense);                                            // G1

    // ---------------- skip decision (uniform: all read same complete counter) ----------------
    if (tid == 0) {
        unsigned ct = g_sel[2];
        shSkip = (ct >= TOPK && ct <= CAND_CAP) ? 1 : 0;
        shC = ct;
    }
    __syncthreads();
    int skip = shSkip;
    if (!skip) {
        // ---- fallback (correct, barrier-balanced; not hit on this data) ----
        unsigned* h = (unsigned*)dynbuf;
        for (int k = tid; k < NB; k += NTHR) h[k] = 0u;
        __syncthreads();
        for (int p = bid * NTHR + tid; p < n4; p += GRID * NTHR) {
            float4 v = sc4[p];
            float vs[4] = { v.x, v.y, v.z, v.w };
#pragma unroll
            for (int l = 0; l < 4; l++)
                if (vs[l] > 0.05f) atomicAdd(&h[bin_of(__float_as_uint(vs[l]))], 1u);
        }
        __syncthreads();
        for (int k = tid; k < NB; k += NTHR) {
            unsigned v = h[k];
            if (v) atomicAdd(&g_hist1[k], v);
        }
        gbar(&shSense);                                        // Gf1
        if (bid == 0 && tid == 0) {
            unsigned cum = 0; int B1 = -1;
            for (int b = NB - 1; b >= 0; b--) {
                unsigned c = g_hist1[b];
                if (cum + c >= TOPK) { B1 = b; break; }
                cum += c;
            }
            if (B1 < 0) B1 = 0;
            g_sel[0] = (unsigned)B1;
            g_sel[2] = 0u;
        }
        gbar(&shSense);                                        // Gf2
        {
            unsigned B1 = g_sel[0];
            for (int p = bid * NTHR + tid; p < n4; p += GRID * NTHR) {
                float4 v = sc4[p];
                float vs[4] = { v.x, v.y, v.z, v.w };
#pragma unroll
                for (int l = 0; l < 4; l++) {
                    float s = vs[l];
                    if (s > 0.05f) {
                        unsigned fb = __float_as_uint(s);
                        if (bin_of(fb) >= (int)B1) {
                            unsigned pos = atomicAdd(&g_sel[2], 1u);
                            if (pos < CAND_CAP) {
                                unsigned idx = (unsigned)(p * 4 + l);
                                g_cand[pos] = ((unsigned long long)fb << 32) |
                                              (unsigned long long)(0xFFFFFFFFu - idx);
                            }
                        }
                    }
                }
            }
        }
        gbar(&shSense);                                        // Gf3
        if (tid == 0) shC = g_sel[2];
        gbar(&shSense);                                        // Gf4 (pad -> even)
        __syncthreads();
    }

    // ---------------- P2: select (16-lane rank) + inline prep ----------------
    {
        unsigned C = shC;
        if (C > CAND_CAP) C = CAND_CAP;
        unsigned long long* sk = (unsigned long long*)dynbuf;  // SELCAP u64
        bool small = (C <= SELCAP);
        const unsigned long long* base;
        if (small) {
            for (unsigned k = (unsigned)tid; k < C; k += NTHR) sk[k] = g_cand[k];
            base = sk;
        } else {
            base = g_cand;
        }
        __syncthreads();
        unsigned lane  = (unsigned)tid & 15u;
        unsigned gidx  = (unsigned)(bid * NTHR + tid) >> 4;
        unsigned cstr  = (unsigned)(GRID * NTHR) >> 4;
        unsigned nIter = (C + cstr - 1) / cstr;                // uniform across grid
        for (unsigned it = 0; it < nIter; it++) {
            unsigned c = gidx + it * cstr;
            bool act = (c < C);
            unsigned long long key = act ? base[c] : 0ULL;
            unsigned rank = 0;
            unsigned k = lane;
            for (; k + 48 < C; k += 64) {
                unsigned long long a0 = base[k], a1 = base[k+16], a2 = base[k+32], a3 = base[k+48];
                rank += (a0 > key) + (a1 > key) + (a2 > key) + (a3 > key);
            }
            for (; k < C; k += 16) rank += (base[k] > key) ? 1u : 0u;
            rank += __shfl_down_sync(0xffffffffu, rank, 8, 16);
            rank += __shfl_down_sync(0xffffffffu, rank, 4, 16);
            rank += __shfl_down_sync(0xffffffffu, rank, 2, 16);
            rank += __shfl_down_sync(0xffffffffu, rank, 1, 16);
            if (act && lane == 0 && rank < TOPK) {
                int idx = (int)(0xFFFFFFFFu - (unsigned)(key & 0xFFFFFFFFull));
                g_topIdx[rank] = idx;
                g_topVal[rank] = __uint_as_float((unsigned)(key >> 32));
                prep_row((int)rank, idx, boxes, labels);       // inline prep
            }
        }
    }
    gbar(&shSense);                                            // G2

    // ---------------- P3: per-class sieve + clip (one block per class) ----------------
    if (bid < NCLS) {
        unsigned* plist = (unsigned*)dynbuf;                   // pair list in SMEM
        __shared__ int pcnt;
        if (tid == 0) pcnt = 0;
        __syncthreads();
        int n = g_clsCnt[bid];
        if (n > CLSCAP) n = CLSCAP;
        if (n >= 2) {
            const int* cl = &g_clsIdx[bid*CLSCAP];
            for (int t = tid; t < n*n; t += NTHR) {
                int i_ = t / n, j_ = t - i_ * n;
                if (i_ >= j_) continue;
                int a = cl[i_], b = cl[j_];
                if (a > b) { int tmp = a; a = b; b = tmp; }
                const float M = 1.0f;
                if (g_aabb[a*4+0] > g_aabb[b*4+1] + M || g_aabb[b*4+0] > g_aabb[a*4+1] + M ||
                    g_aabb[a*4+2] > g_aabb[b*4+3] + M || g_aabb[b*4+2] > g_aabb[a*4+3] + M) continue;
                int pos = atomicAdd(&pcnt, 1);
                if (pos < PAIR_SH) plist[pos] = ((unsigned)a << 16) | (unsigned)b;
            }
        }
        __syncthreads();
        int W = pcnt; if (W > PAIR_SH) W = PAIR_SH;
        int lane = tid & 31;
        int wid  = tid >> 5;
        for (int c = wid; c < W; c += NTHR/32) {
            unsigned e = plist[c];
            int i = (int)(e >> 16), j = (int)(e & 0xFFFFu);
            float inter = warp_inter_area(i, j, lane);
            if (lane == 0) {
                float S   = __fadd_rn(__fsub_rn(__fadd_rn(g_area[i], g_area[j]), inter), 1e-6f);
                float iou = inter / S;
                if (iou > 0.5f) {
                    unsigned pos = atomicAdd(&g_sel[5], 1u);
                    if (pos < SPCAP) g_supPairs[pos] = e;
                }
            }
        }
    }
    gbar(&shSense);                                            // G3

    // ---------------- P4: block 0 — slot-compacted NMS + output + self-clean ----------------
    if (bid == 0) {
        __shared__ unsigned keepW[32];
        __shared__ unsigned raW[32];
        __shared__ unsigned wbase[32];
        __shared__ int lst[DETS];
        __shared__ int kcnt;
        __shared__ int nslots;
        unsigned* mask = (unsigned*)dynbuf;                    // 32KB within dynbuf
        if (tid < 32) { keepW[tid] = 0u; raW[tid] = 0u; }
        __syncthreads();
        for (int i = tid; i < TOPK; i += NTHR)
            if (g_topVal[i] > neginf()) atomicOr(&keepW[i >> 5], 1u << (i & 31));
        unsigned P = g_sel[5];
        if (P > SPCAP) P = SPCAP;
        for (unsigned p = (unsigned)tid; p < P; p += NTHR) {
            unsigned i = g_supPairs[p] >> 16;
            atomicOr(&raW[i >> 5], 1u << (i & 31));
        }
        __syncthreads();
        if (tid < 32) {
            unsigned cnt = __popc(raW[tid]);
            unsigned ex = cnt;
#pragma unroll
            for (int d = 1; d < 32; d <<= 1) {
                unsigned v = __shfl_up_sync(0xffffffffu, ex, d);
                if (tid >= d) ex += v;
            }
            wbase[tid] = ex - cnt;
            if (tid == 31) nslots = (int)ex;
        }
        __syncthreads();
        int NS = nslots;
        if (NS <= MAXSLOTS) {
            for (int k = tid; k < NS * 32; k += NTHR) mask[k] = 0u;
            __syncthreads();
            for (unsigned p = (unsigned)tid; p < P; p += NTHR) {
                unsigned e = g_supPairs[p];
                unsigned i = e >> 16, j = e & 0xFFFFu;
                unsigned w = i >> 5, b = i & 31;
                unsigned slot = wbase[w] + __popc(raW[w] & ((1u << b) - 1u));
                atomicOr(&mask[slot * 32 + (j >> 5)], 1u << (j & 31));
            }
            __syncthreads();
            if (tid < 32) {
                int s = 0;
                for (int w = 0; w < 32; w++) {
                    unsigned rb = raW[w];
                    while (rb) {
                        int b = __ffs(rb) - 1;
                        rb &= rb - 1;
                        bool kept = (keepW[w] >> b) & 1u;
                        if (kept) keepW[tid] &= ~mask[s * 32 + tid];
                        s++;
                        __syncwarp();
                    }
                }
            }
        } else if (tid == 0) {
            for (int w = 0; w < 32; w++) {
                unsigned rb = raW[w];
                while (rb) {
                    int b = __ffs(rb) - 1;
                    rb &= rb - 1;
                    int i = w * 32 + b;
                    if (keepW[w] & (1u << b)) {
                        for (unsigned p = 0; p < P; p++) {
                            unsigned e = g_supPairs[p];
                            if ((int)(e >> 16) == i) {
                                int j = (int)(e & 0xFFFFu);
                                keepW[j >> 5] &= ~(1u << (j & 31));
                            }
                        }
                    }
                }
            }
        }
        __syncthreads();
        if (tid == 0) {
            int p = 0;
            for (int w = 0; w < 32 && p < DETS; w++) {
                unsigned m = keepW[w];
                while (m && p < DETS) {
                    int b = __ffs(m) - 1;
                    m &= m - 1;
                    lst[p++] = w * 32 + b;
                }
            }
            kcnt = p;
        }
        __syncthreads();
        for (int r = tid; r < DETS; r += NTHR) {
            if (r < kcnt) {
                int i = lst[r];
#pragma unroll
                for (int k = 0; k < 5; k++) out[r*5+k] = g_bk[i*5+k];
                out[DETS*5 + r] = (float)g_lab[i];
                out[DETS*6 + r] = g_topVal[i];
            } else {
#pragma unroll
                for (int k = 0; k < 5; k++) out[r*5+k] = 0.0f;
                out[DETS*5 + r] = -1.0f;
                out[DETS*6 + r] = 0.0f;
            }
        }
        // self-clean before final barrier (others wait at G4)
        for (int k = tid; k < 8; k += NTHR) g_sel[k] = 0u;
        for (int c = tid; c < NCLS; c += NTHR) g_clsCnt[c] = 0;
        if (!skip) for (int k = tid; k < NB; k += NTHR) g_hist1[k] = 0u;
        __threadfence();
    }
    gbar(&shSense);                                            // G4 (even count -> sense back to 0)
}

// ---------------------------------------------------------------- launcher: ONE kernel
extern "C" void kernel_launch(void* const* d_in, const int* in_sizes, int n_in,
                              void* d_out, int out_size) {
    const float* boxes  = (const float*)d_in[0];
    const float* scores = (const float*)d_in[1];
    const int*   labels = (const int*)d_in[2];
    int n = in_sizes[1];
    int n4 = n / 4;

    static const int DYN = SELCAP * 8;   // 49152 B
    cudaFuncSetAttribute(k_all, cudaFuncAttributeMaxDynamicSharedMemorySize, DYN);
    k_all<<<GRID, NTHR, DYN>>>(boxes, (const float4*)scores, labels, (float*)d_out, n4);
}

// round 15
// speedup vs baseline: 1.2010x; 1.0525x over previous
#include <cuda_runtime.h>
#include <stdint.h>
#include <math.h>

#define TOPK 1000
#define DETS 300
#define NB    4608          // fallback bins via fb>>13 - BASE
#define BASE  125542        // 0x3D4CCCCD >> 13  (0.05f)
#define CAND_CAP 32768
#define SELCAP   6144
#define NCLS  80
#define CLSCAP 1024
#define PAIR_SH 2048
#define SPCAP 8192
#define MAXSLOTS 256
#define FAST_T 0.999f
#define GRID  132
#define NTHR  256

__device__ unsigned          g_barCount;
__device__ volatile unsigned g_barSense;
__device__ volatile unsigned g_doneCnt;
__device__ unsigned          g_hist1[NB];
__device__ unsigned          g_sel[8];     // [0]=B1 bin  [2]=cand cnt  [5]=sup cnt
__device__ unsigned long long g_cand[CAND_CAP];
__device__ unsigned          g_supPairs[SPCAP];
__device__ int               g_topIdx[TOPK];
__device__ float             g_topVal[TOPK];
__device__ float             g_bk[TOPK*5];
__device__ float             g_nms[TOPK*5];
__device__ float             g_corn[TOPK*8];
__device__ float             g_aabb[TOPK*4];
__device__ float             g_area[TOPK];
__device__ int               g_clsCnt[NCLS];
__device__ int               g_clsIdx[NCLS*CLSCAP];
__device__ int               g_lab[TOPK];

__device__ __forceinline__ float neginf() { return __int_as_float(0xff800000); }

__device__ __forceinline__ int bin_of(unsigned fb) {
    int b = (int)(fb >> 13) - BASE;
    if (b < 0) b = 0;
    if (b > NB - 1) b = NB - 1;
    return b;
}

__device__ __forceinline__ float sel4(int i, float a, float b, float c, float d) {
    return (i == 0) ? a : (i == 1) ? b : (i == 2) ? c : d;
}

// sense-reversing software grid barrier (all blocks co-resident: GRID <= #SM)
__device__ __forceinline__ void gbar(unsigned* shSense) {
    __syncthreads();
    if (threadIdx.x == 0) {
        unsigned s = *shSense ^ 1u;
        *shSense = s;
        __threadfence();
        unsigned arrived = atomicAdd(&g_barCount, 1u) + 1u;
        if (arrived == (unsigned)gridDim.x) {
            atomicExch(&g_barCount, 0u);
            __threadfence();
            g_barSense = s;
        } else {
            while (g_barSense != s) __nanosleep(32);
        }
        __threadfence();
    }
    __syncthreads();
}

// ---------------------------------------------------------------- warp-cooperative exact clip (bitwise == scalar reference replica)
__device__ __forceinline__ float warp_inter_area(int bi, int bj, int lane) {
    const unsigned FULL = 0xffffffffu;
    const float eps = 1e-6f;
    const float ONEPE = 1.000001f;
    const float* A  = &g_nms[bi*5];
    const float* B  = &g_nms[bj*5];
    const float* cA = &g_corn[bi*8];
    const float* cB = &g_corn[bj*8];
    float ax0=cA[0], ay0=cA[1], ax1=cA[2], ay1=cA[3], ax2=cA[4], ay2=cA[5], ax3=cA[6], ay3=cA[7];
    float bx0=cB[0], by0=cB[1], bx1=cB[2], by1=cB[3], bx2=cB[4], by2=cB[5], bx3=cB[6], by3=cB[7];
    float Acx=A[0], Acy=A[1], Aw=A[2], Ah=A[3], Aa=A[4];
    float Bcx=B[0], Bcy=B[1], Bw=B[2], Bh=B[3], Ba=B[4];

    float dAx0=__fsub_rn(ax1,ax0), dAy0=__fsub_rn(ay1,ay0);
    float dAx1=__fsub_rn(ax2,ax1), dAy1=__fsub_rn(ay2,ay1);
    float dAx2=__fsub_rn(ax3,ax2), dAy2=__fsub_rn(ay3,ay2);
    float dAx3=__fsub_rn(ax0,ax3), dAy3=__fsub_rn(ay0,ay3);
    float dBx0=__fsub_rn(bx1,bx0), dBy0=__fsub_rn(by1,by0);
    float dBx1=__fsub_rn(bx2,bx1), dBy1=__fsub_rn(by2,by1);
    float dBx2=__fsub_rn(bx3,bx2), dBy2=__fsub_rn(by3,by2);
    float dBx3=__fsub_rn(bx0,bx3), dBy3=__fsub_rn(by0,by3);

    float px = 0.0f, py = 0.0f;
    bool  vl = false;
    if (lane < 8) {
        int  c4  = lane & 3;
        bool isA = lane < 4;
        float ptx = isA ? sel4(c4, ax0,ax1,ax2,ax3) : sel4(c4, bx0,bx1,bx2,bx3);
        float pty = isA ? sel4(c4, ay0,ay1,ay2,ay3) : sel4(c4, by0,by1,by2,by3);
        float tcx = isA ? Bcx : Acx;
        float tcy = isA ? Bcy : Acy;
        float tw  = isA ? Bw  : Aw;
        float th  = isA ? Bh  : Ah;
        float ta  = isA ? Ba  : Aa;
        float cc = cosf(ta), ss = sinf(ta);
        float rx = __fsub_rn(ptx, tcx), ry = __fsub_rn(pty, tcy);
        float xr = __fadd_rn(__fmul_rn(rx, cc), __fmul_rn(ry, ss));
        float yr = __fadd_rn(__fmul_rn(-rx, ss), __fmul_rn(ry, cc));
        float lw = __fadd_rn(__fmul_rn(tw, 0.5f), eps);
        float lh = __fadd_rn(__fmul_rn(th, 0.5f), eps);
        vl = (fabsf(xr) <= lw) && (fabsf(yr) <= lh);
        px = ptx; py = pty;
    } else if (lane < 24) {
        int ii = (lane - 8) >> 2, jj = (lane - 8) & 3;
        float axi = sel4(ii, ax0,ax1,ax2,ax3), ayi = sel4(ii, ay0,ay1,ay2,ay3);
        float dxi = sel4(ii, dAx0,dAx1,dAx2,dAx3), dyi = sel4(ii, dAy0,dAy1,dAy2,dAy3);
        float bxj = sel4(jj, bx0,bx1,bx2,bx3), byj = sel4(jj, by0,by1,by2,by3);
        float exj = sel4(jj, dBx0,dBx1,dBx2,dBx3), eyj = sel4(jj, dBy0,dBy1,dBy2,dBy3);
        float rx  = __fsub_rn(bxj, axi), ry = __fsub_rn(byj, ayi);
        float den = __fsub_rn(__fmul_rn(dxi, eyj), __fmul_rn(dyi, exj));
        float ad  = fabsf(den);
        float dens = (ad < 1e-9f) ? 1.0f : den;
        float t = __fsub_rn(__fmul_rn(rx, eyj), __fmul_rn(ry, exj)) / dens;
        float u = __fsub_rn(__fmul_rn(rx, dyi), __fmul_rn(ry, dxi)) / dens;
        vl = (ad > 1e-9f) && (t >= -eps) && (t <= ONEPE) && (u >= -eps) && (u <= ONEPE);
        px = __fadd_rn(axi, __fmul_rn(t, dxi));
        py = __fadd_rn(ayi, __fmul_rn(t, dyi));
    }

    unsigned bal = __ballot_sync(FULL, vl) & 0x00FFFFFFu;
    int cnt = __popc(bal);

    float f = vl ? 1.0f : 0.0f;
    float contx = __fmul_rn(px, f);
    float conty = __fmul_rn(py, f);
    float sx = 0.0f, sy = 0.0f;
#pragma unroll
    for (int m = 0; m < 24; m++) {
        float vx = __shfl_sync(FULL, contx, m);
        float vy = __shfl_sync(FULL, conty, m);
        sx = __fadd_rn(sx, vx);
        sy = __fadd_rn(sy, vy);
    }
    int cm = cnt > 1 ? cnt : 1;
    float cenx = sx / (float)cm, ceny = sy / (float)cm;

    int am = bal ? (__ffs(bal) - 1) : 0;
    float anx  = __shfl_sync(FULL, px, am);
    float anyy = __shfl_sync(FULL, py, am);

    float qx = vl ? px : anx;
    float qy = vl ? py : anyy;
    float ang = atan2f(__fsub_rn(qy, ceny), __fsub_rn(qx, cenx));

    int rank = (lane < 24) ? 0 : (100 + lane);
#pragma unroll
    for (int m = 0; m < 24; m++) {
        float am_ = __shfl_sync(FULL, ang, m);
        if (lane < 24 && m != lane) {
            bool less = (am_ < ang) || (am_ == ang && m < lane);
            rank += less ? 1 : 0;
        }
    }

    float X = 0.0f, Y = 0.0f;
#pragma unroll
    for (int m = 0; m < 24; m++) {
        int   rm = __shfl_sync(FULL, rank, m);
        float xm = __shfl_sync(FULL, qx, m);
        float ym = __shfl_sync(FULL, qy, m);
        if (rm == lane) { X = xm; Y = ym; }
    }
    int nxt = (lane == 23) ? 0 : lane + 1;
    float Xn = __shfl_sync(FULL, X, nxt);
    float Yn = __shfl_sync(FULL, Y, nxt);
    float term = __fsub_rn(__fmul_rn(X, Yn), __fmul_rn(Xn, Y));

    float ssum = 0.0f;
#pragma unroll
    for (int m = 0; m < 24; m++) {
        float tv = __shfl_sync(FULL, term, m);
        ssum = __fadd_rn(ssum, tv);
    }
    float area = __fmul_rn(0.5f, fabsf(ssum));
    return (cnt >= 3) ? area : 0.0f;
}

// prep one selected row (rank r, source idx): gather + offset + corners + AABB + class insert
__device__ __forceinline__ void prep_row(int r, int idx, const float* __restrict__ boxes,
                                         const int* __restrict__ labels) {
    float cx = boxes[idx*5+0], cy = boxes[idx*5+1];
    float w  = boxes[idx*5+2], h  = boxes[idx*5+3];
    float a  = boxes[idx*5+4];
    g_bk[r*5+0]=cx; g_bk[r*5+1]=cy; g_bk[r*5+2]=w; g_bk[r*5+3]=h; g_bk[r*5+4]=a;
    int lab = labels[idx];
    g_lab[r] = lab;
    float off = __fmul_rn((float)lab, 10000.0f);
    float cxo = __fadd_rn(cx, off);
    float cyo = __fadd_rn(cy, off);
    g_nms[r*5+0]=cxo; g_nms[r*5+1]=cyo; g_nms[r*5+2]=w; g_nms[r*5+3]=h; g_nms[r*5+4]=a;
    g_area[r] = __fmul_rn(w, h);
    float c = cosf(a), s = sinf(a);
    float dx = __fmul_rn(w, 0.5f), dy = __fmul_rn(h, 0.5f);
    float ox[4] = { dx, -dx, -dx,  dx };
    float oy[4] = { dy,  dy, -dy, -dy };
    float mnx =  3.4e38f, mxx = -3.4e38f, mny = 3.4e38f, mxy = -3.4e38f;
#pragma unroll
    for (int j = 0; j < 4; j++) {
        float x = __fsub_rn(__fadd_rn(cxo, __fmul_rn(ox[j], c)), __fmul_rn(oy[j], s));
        float y = __fadd_rn(__fadd_rn(cyo, __fmul_rn(ox[j], s)), __fmul_rn(oy[j], c));
        g_corn[r*8 + 2*j]     = x;
        g_corn[r*8 + 2*j + 1] = y;
        mnx = fminf(mnx, x); mxx = fmaxf(mxx, x);
        mny = fminf(mny, y); mxy = fmaxf(mxy, y);
    }
    g_aabb[r*4+0]=mnx; g_aabb[r*4+1]=mxx; g_aabb[r*4+2]=mny; g_aabb[r*4+3]=mxy;
    if (lab >= 0 && lab < NCLS) {
        int pos = atomicAdd(&g_clsCnt[lab], 1);
        if (pos < CLSCAP) g_clsIdx[lab*CLSCAP + pos] = r;
    }
}

// ---------------------------------------------------------------- ONE persistent kernel, 2 grid barriers + done-counter
extern __shared__ unsigned char dynbuf[];   // 49152 B

__global__ void __launch_bounds__(NTHR, 2)
k_all(const float* __restrict__ boxes, const float4* __restrict__ sc4,
      const int* __restrict__ labels, float* __restrict__ out, int n4) {
    __shared__ unsigned shSense;
    __shared__ unsigned shC;
    __shared__ int shSkip;
    int tid = threadIdx.x;
    int bid = blockIdx.x;
    if (tid == 0) shSense = 0u;
    __syncthreads();

    // ---------------- P1: default-init + fast compact (s > FAST_T), MLP=8 ----------------
    {
        int gid = bid * NTHR + tid;
        int S   = GRID * NTHR;
        for (int i = gid; i < TOPK; i += S) {
            g_topIdx[i] = -1;
            g_topVal[i] = neginf();
        }
        for (int p = gid; p < n4; p += 8 * S) {
            float4 vv[8];
            int    pp[8];
#pragma unroll
            for (int q = 0; q < 8; q++) {
                pp[q] = p + q * S;
                vv[q] = (pp[q] < n4) ? sc4[pp[q]] : make_float4(0,0,0,0);
            }
#pragma unroll
            for (int q = 0; q < 8; q++) {
                float vs[4] = { vv[q].x, vv[q].y, vv[q].z, vv[q].w };
#pragma unroll
                for (int l = 0; l < 4; l++) {
                    float s = vs[l];
                    if (s > FAST_T) {
                        unsigned pos = atomicAdd(&g_sel[2], 1u);
                        if (pos < CAND_CAP) {
                            unsigned idx = (unsigned)(pp[q] * 4 + l);
                            g_cand[pos] = ((unsigned long long)__float_as_uint(s) << 32) |
                                          (unsigned long long)(0xFFFFFFFFu - idx);
                        }
                    }
                }
            }
        }
    }
    gbar(&shSense);                                            // G1

    // ---------------- skip decision ----------------
    if (tid == 0) {
        unsigned ct = g_sel[2];
        shSkip = (ct >= TOPK && ct <= CAND_CAP) ? 1 : 0;
        shC = ct;
    }
    __syncthreads();
    int skip = shSkip;
    if (!skip) {
        // ---- fallback (correct, barrier-balanced; not hit on this data) ----
        unsigned* h = (unsigned*)dynbuf;
        for (int k = tid; k < NB; k += NTHR) h[k] = 0u;
        __syncthreads();
        for (int p = bid * NTHR + tid; p < n4; p += GRID * NTHR) {
            float4 v = sc4[p];
            float vs[4] = { v.x, v.y, v.z, v.w };
#pragma unroll
            for (int l = 0; l < 4; l++)
                if (vs[l] > 0.05f) atomicAdd(&h[bin_of(__float_as_uint(vs[l]))], 1u);
        }
        __syncthreads();
        for (int k = tid; k < NB; k += NTHR) {
            unsigned v = h[k];
            if (v) atomicAdd(&g_hist1[k], v);
        }
        gbar(&shSense);                                        // Gf1
        if (bid == 0 && tid == 0) {
            unsigned cum = 0; int B1 = -1;
            for (int b = NB - 1; b >= 0; b--) {
                unsigned c = g_hist1[b];
                if (cum + c >= TOPK) { B1 = b; break; }
                cum += c;
            }
            if (B1 < 0) B1 = 0;
            g_sel[0] = (unsigned)B1;
            g_sel[2] = 0u;
        }
        gbar(&shSense);                                        // Gf2
        {
            unsigned B1 = g_sel[0];
            for (int p = bid * NTHR + tid; p < n4; p += GRID * NTHR) {
                float4 v = sc4[p];
                float vs[4] = { v.x, v.y, v.z, v.w };
#pragma unroll
                for (int l = 0; l < 4; l++) {
                    float s = vs[l];
                    if (s > 0.05f) {
                        unsigned fb = __float_as_uint(s);
                        if (bin_of(fb) >= (int)B1) {
                            unsigned pos = atomicAdd(&g_sel[2], 1u);
                            if (pos < CAND_CAP) {
                                unsigned idx = (unsigned)(p * 4 + l);
                                g_cand[pos] = ((unsigned long long)fb << 32) |
                                              (unsigned long long)(0xFFFFFFFFu - idx);
                            }
                        }
                    }
                }
            }
        }
        gbar(&shSense);                                        // Gf3
        if (tid == 0) shC = g_sel[2];
        gbar(&shSense);                                        // Gf4 (pad -> even flips)
        __syncthreads();
    }

    // ---------------- P2: select (16-lane rank) + inline prep ----------------
    {
        unsigned C = shC;
        if (C > CAND_CAP) C = CAND_CAP;
        unsigned long long* sk = (unsigned long long*)dynbuf;  // SELCAP u64
        bool small = (C <= SELCAP);
        const unsigned long long* base;
        if (small) {
            for (unsigned k = (unsigned)tid; k < C; k += NTHR) sk[k] = g_cand[k];
            base = sk;
        } else {
            base = g_cand;
        }
        __syncthreads();
        unsigned lane  = (unsigned)tid & 15u;
        unsigned gidx  = (unsigned)(bid * NTHR + tid) >> 4;
        unsigned cstr  = (unsigned)(GRID * NTHR) >> 4;
        unsigned nIter = (C + cstr - 1) / cstr;                // uniform across grid
        for (unsigned it = 0; it < nIter; it++) {
            unsigned c = gidx + it * cstr;
            bool act = (c < C);
            unsigned long long key = act ? base[c] : 0ULL;
            unsigned rank = 0;
            unsigned k = lane;
            for (; k + 48 < C; k += 64) {
                unsigned long long a0 = base[k], a1 = base[k+16], a2 = base[k+32], a3 = base[k+48];
                rank += (a0 > key) + (a1 > key) + (a2 > key) + (a3 > key);
            }
            for (; k < C; k += 16) rank += (base[k] > key) ? 1u : 0u;
            rank += __shfl_down_sync(0xffffffffu, rank, 8, 16);
            rank += __shfl_down_sync(0xffffffffu, rank, 4, 16);
            rank += __shfl_down_sync(0xffffffffu, rank, 2, 16);
            rank += __shfl_down_sync(0xffffffffu, rank, 1, 16);
            if (act && lane == 0 && rank < TOPK) {
                int idx = (int)(0xFFFFFFFFu - (unsigned)(key & 0xFFFFFFFFull));
                g_topIdx[rank] = idx;
                g_topVal[rank] = __uint_as_float((unsigned)(key >> 32));
                prep_row((int)rank, idx, boxes, labels);       // inline prep
            }
        }
    }
    gbar(&shSense);                                            // G2

    // ---------------- P3: per-class sieve + clip (one block per class) ----------------
    if (bid < NCLS) {
        unsigned* plist = (unsigned*)dynbuf;                   // pair list in SMEM
        __shared__ int pcnt;
        if (tid == 0) pcnt = 0;
        __syncthreads();
        int n = g_clsCnt[bid];
        if (n > CLSCAP) n = CLSCAP;
        if (n >= 2) {
            const int* cl = &g_clsIdx[bid*CLSCAP];
            for (int t = tid; t < n*n; t += NTHR) {
                int i_ = t / n, j_ = t - i_ * n;
                if (i_ >= j_) continue;
                int a = cl[i_], b = cl[j_];
                if (a > b) { int tmp = a; a = b; b = tmp; }
                const float M = 1.0f;
                if (g_aabb[a*4+0] > g_aabb[b*4+1] + M || g_aabb[b*4+0] > g_aabb[a*4+1] + M ||
                    g_aabb[a*4+2] > g_aabb[b*4+3] + M || g_aabb[b*4+2] > g_aabb[a*4+3] + M) continue;
                int pos = atomicAdd(&pcnt, 1);
                if (pos < PAIR_SH) plist[pos] = ((unsigned)a << 16) | (unsigned)b;
            }
        }
        __syncthreads();
        int W = pcnt; if (W > PAIR_SH) W = PAIR_SH;
        int lane = tid & 31;
        int wid  = tid >> 5;
        for (int c = wid; c < W; c += NTHR/32) {
            unsigned e = plist[c];
            int i = (int)(e >> 16), j = (int)(e & 0xFFFFu);
            float inter = warp_inter_area(i, j, lane);
            if (lane == 0) {
                float S   = __fadd_rn(__fsub_rn(__fadd_rn(g_area[i], g_area[j]), inter), 1e-6f);
                float iou = inter / S;
                if (iou > 0.5f) {
                    unsigned pos = atomicAdd(&g_sel[5], 1u);
                    if (pos < SPCAP) g_supPairs[pos] = e;
                }
            }
        }
    }

    // ---------------- half-barrier: blocks signal done and exit; block 0 proceeds ----------------
    __threadfence();
    __syncthreads();
    if (tid == 0) atomicAdd((unsigned*)&g_doneCnt, 1u);
    if (bid != 0) return;
    if (tid == 0) {
        while (g_doneCnt < (unsigned)GRID) __nanosleep(32);
    }
    __syncthreads();
    __threadfence();

    // ---------------- P4: block 0 — slot-compacted NMS + output + self-clean ----------------
    {
        __shared__ unsigned keepW[32];
        __shared__ unsigned raW[32];
        __shared__ unsigned wbase[32];
        __shared__ int lst[DETS];
        __shared__ int kcnt;
        __shared__ int nslots;
        unsigned* mask = (unsigned*)dynbuf;                    // 32KB within dynbuf
        if (tid < 32) { keepW[tid] = 0u; raW[tid] = 0u; }
        __syncthreads();
        for (int i = tid; i < TOPK; i += NTHR)
            if (g_topVal[i] > neginf()) atomicOr(&keepW[i >> 5], 1u << (i & 31));
        unsigned P = g_sel[5];
        if (P > SPCAP) P = SPCAP;
        for (unsigned p = (unsigned)tid; p < P; p += NTHR) {
            unsigned i = g_supPairs[p] >> 16;
            atomicOr(&raW[i >> 5], 1u << (i & 31));
        }
        __syncthreads();
        if (tid < 32) {
            unsigned cnt = __popc(raW[tid]);
            unsigned ex = cnt;
#pragma unroll
            for (int d = 1; d < 32; d <<= 1) {
                unsigned v = __shfl_up_sync(0xffffffffu, ex, d);
                if (tid >= d) ex += v;
            }
            wbase[tid] = ex - cnt;
            if (tid == 31) nslots = (int)ex;
        }
        __syncthreads();
        int NS = nslots;
        if (NS <= MAXSLOTS) {
            for (int k = tid; k < NS * 32; k += NTHR) mask[k] = 0u;
            __syncthreads();
            for (unsigned p = (unsigned)tid; p < P; p += NTHR) {
                unsigned e = g_supPairs[p];
                unsigned i = e >> 16, j = e & 0xFFFFu;
                unsigned w = i >> 5, b = i & 31;
                unsigned slot = wbase[w] + __popc(raW[w] & ((1u << b) - 1u));
                atomicOr(&mask[slot * 32 + (j >> 5)], 1u << (j & 31));
            }
            __syncthreads();
            if (tid < 32) {
                int s = 0;
                for (int w = 0; w < 32; w++) {
                    unsigned rb = raW[w];
                    while (rb) {
                        int b = __ffs(rb) - 1;
                        rb &= rb - 1;
                        bool kept = (keepW[w] >> b) & 1u;
                        if (kept) keepW[tid] &= ~mask[s * 32 + tid];
                        s++;
                        __syncwarp();
                    }
                }
            }
        } else if (tid == 0) {
            for (int w = 0; w < 32; w++) {
                unsigned rb = raW[w];
                while (rb) {
                    int b = __ffs(rb) - 1;
                    rb &= rb - 1;
                    int i = w * 32 + b;
                    if (keepW[w] & (1u << b)) {
                        for (unsigned p = 0; p < P; p++) {
                            unsigned e = g_supPairs[p];
                            if ((int)(e >> 16) == i) {
                                int j = (int)(e & 0xFFFFu);
                                keepW[j >> 5] &= ~(1u << (j & 31));
                            }
                        }
                    }
                }
            }
        }
        __syncthreads();
        if (tid == 0) {
            int p = 0;
            for (int w = 0; w < 32 && p < DETS; w++) {
                unsigned m = keepW[w];
                while (m && p < DETS) {
                    int b = __ffs(m) - 1;
                    m &= m - 1;
                    lst[p++] = w * 32 + b;
                }
            }
            kcnt = p;
        }
        __syncthreads();
        for (int r = tid; r < DETS; r += NTHR) {
            if (r < kcnt) {
                int i = lst[r];
#pragma unroll
                for (int k = 0; k < 5; k++) out[r*5+k] = g_bk[i*5+k];
                out[DETS*5 + r] = (float)g_lab[i];
                out[DETS*6 + r] = g_topVal[i];
            } else {
#pragma unroll
                for (int k = 0; k < 5; k++) out[r*5+k] = 0.0f;
                out[DETS*5 + r] = -1.0f;
                out[DETS*6 + r] = 0.0f;
            }
        }
        // full self-clean for next replay (all other blocks already done)
        for (int k = tid; k < 8; k += NTHR) g_sel[k] = 0u;
        for (int c = tid; c < NCLS; c += NTHR) g_clsCnt[c] = 0;
        if (!skip) for (int k = tid; k < NB; k += NTHR) g_hist1[k] = 0u;
        __syncthreads();
        if (tid == 0) g_doneCnt = 0u;
    }
}

// ---------------------------------------------------------------- launcher: ONE kernel
extern "C" void kernel_launch(void* const* d_in, const int* in_sizes, int n_in,
                              void* d_out, int out_size) {
    const float* boxes  = (const float*)d_in[0];
    const float* scores = (const float*)d_in[1];
    const int*   labels = (const int*)d_in[2];
    int n = in_sizes[1];
    int n4 = n / 4;

    static const int DYN = SELCAP * 8;   // 49152 B
    cudaFuncSetAttribute(k_all, cudaFuncAttributeMaxDynamicSharedMemorySize, DYN);
    k_all<<<GRID, NTHR, DYN>>>(boxes, (const float4*)scores, labels, (float*)d_out, n4);
}

// round 16
// speedup vs baseline: 1.3393x; 1.1152x over previous
#include <cuda_runtime.h>
#include <stdint.h>
#include <math.h>

#define TOPK 1000
#define DETS 300
#define NB    4608          // fallback bins via fb>>13 - BASE
#define BASE  125542        // 0x3D4CCCCD >> 13  (0.05f)
#define CAND_CAP 32768
#define SELCAP   6144
#define NCLS  80
#define CLSCAP 1024
#define PAIR_SH 2048
#define SPCAP 8192
#define MAXSLOTS 256
#define FAST_T 0.999f
#define GRID  132
#define NTHR  512

__device__ unsigned          g_barCount;
__device__ volatile unsigned g_barSense;
__device__ volatile unsigned g_doneCnt;
__device__ unsigned          g_hist1[NB];
__device__ unsigned          g_sel[8];     // [0]=B1 bin  [2]=cand cnt  [5]=sup cnt
__device__ unsigned long long g_cand[CAND_CAP];
__device__ unsigned          g_supPairs[SPCAP];
__device__ int               g_topIdx[TOPK];
__device__ float             g_topVal[TOPK];
__device__ float             g_bk[TOPK*5];
__device__ float             g_nms[TOPK*5];
__device__ float             g_corn[TOPK*8];
__device__ float             g_aabb[TOPK*4];
__device__ float             g_area[TOPK];
__device__ int               g_clsCnt[NCLS];
__device__ int               g_clsIdx[NCLS*CLSCAP];
__device__ int               g_lab[TOPK];

__device__ __forceinline__ float neginf() { return __int_as_float(0xff800000); }

__device__ __forceinline__ int bin_of(unsigned fb) {
    int b = (int)(fb >> 13) - BASE;
    if (b < 0) b = 0;
    if (b > NB - 1) b = NB - 1;
    return b;
}

__device__ __forceinline__ float sel4(int i, float a, float b, float c, float d) {
    return (i == 0) ? a : (i == 1) ? b : (i == 2) ? c : d;
}

// sense-reversing software grid barrier (all blocks co-resident: GRID <= #SM)
__device__ __forceinline__ void gbar(unsigned* shSense) {
    __syncthreads();
    if (threadIdx.x == 0) {
        unsigned s = *shSense ^ 1u;
        *shSense = s;
        __threadfence();
        unsigned arrived = atomicAdd(&g_barCount, 1u) + 1u;
        if (arrived == (unsigned)gridDim.x) {
            atomicExch(&g_barCount, 0u);
            __threadfence();
            g_barSense = s;
        } else {
            while (g_barSense != s) __nanosleep(32);
        }
        __threadfence();
    }
    __syncthreads();
}

// ---------------------------------------------------------------- warp-cooperative exact clip (bitwise == scalar reference replica)
__device__ __forceinline__ float warp_inter_area(int bi, int bj, int lane) {
    const unsigned FULL = 0xffffffffu;
    const float eps = 1e-6f;
    const float ONEPE = 1.000001f;
    const float* A  = &g_nms[bi*5];
    const float* B  = &g_nms[bj*5];
    const float* cA = &g_corn[bi*8];
    const float* cB = &g_corn[bj*8];
    float ax0=cA[0], ay0=cA[1], ax1=cA[2], ay1=cA[3], ax2=cA[4], ay2=cA[5], ax3=cA[6], ay3=cA[7];
    float bx0=cB[0], by0=cB[1], bx1=cB[2], by1=cB[3], bx2=cB[4], by2=cB[5], bx3=cB[6], by3=cB[7];
    float Acx=A[0], Acy=A[1], Aw=A[2], Ah=A[3], Aa=A[4];
    float Bcx=B[0], Bcy=B[1], Bw=B[2], Bh=B[3], Ba=B[4];

    float dAx0=__fsub_rn(ax1,ax0), dAy0=__fsub_rn(ay1,ay0);
    float dAx1=__fsub_rn(ax2,ax1), dAy1=__fsub_rn(ay2,ay1);
    float dAx2=__fsub_rn(ax3,ax2), dAy2=__fsub_rn(ay3,ay2);
    float dAx3=__fsub_rn(ax0,ax3), dAy3=__fsub_rn(ay0,ay3);
    float dBx0=__fsub_rn(bx1,bx0), dBy0=__fsub_rn(by1,by0);
    float dBx1=__fsub_rn(bx2,bx1), dBy1=__fsub_rn(by2,by1);
    float dBx2=__fsub_rn(bx3,bx2), dBy2=__fsub_rn(by3,by2);
    float dBx3=__fsub_rn(bx0,bx3), dBy3=__fsub_rn(by0,by3);

    float px = 0.0f, py = 0.0f;
    bool  vl = false;
    if (lane < 8) {
        int  c4  = lane & 3;
        bool isA = lane < 4;
        float ptx = isA ? sel4(c4, ax0,ax1,ax2,ax3) : sel4(c4, bx0,bx1,bx2,bx3);
        float pty = isA ? sel4(c4, ay0,ay1,ay2,ay3) : sel4(c4, by0,by1,by2,by3);
        float tcx = isA ? Bcx : Acx;
        float tcy = isA ? Bcy : Acy;
        float tw  = isA ? Bw  : Aw;
        float th  = isA ? Bh  : Ah;
        float ta  = isA ? Ba  : Aa;
        float cc = cosf(ta), ss = sinf(ta);
        float rx = __fsub_rn(ptx, tcx), ry = __fsub_rn(pty, tcy);
        float xr = __fadd_rn(__fmul_rn(rx, cc), __fmul_rn(ry, ss));
        float yr = __fadd_rn(__fmul_rn(-rx, ss), __fmul_rn(ry, cc));
        float lw = __fadd_rn(__fmul_rn(tw, 0.5f), eps);
        float lh = __fadd_rn(__fmul_rn(th, 0.5f), eps);
        vl = (fabsf(xr) <= lw) && (fabsf(yr) <= lh);
        px = ptx; py = pty;
    } else if (lane < 24) {
        int ii = (lane - 8) >> 2, jj = (lane - 8) & 3;
        float axi = sel4(ii, ax0,ax1,ax2,ax3), ayi = sel4(ii, ay0,ay1,ay2,ay3);
        float dxi = sel4(ii, dAx0,dAx1,dAx2,dAx3), dyi = sel4(ii, dAy0,dAy1,dAy2,dAy3);
        float bxj = sel4(jj, bx0,bx1,bx2,bx3), byj = sel4(jj, by0,by1,by2,by3);
        float exj = sel4(jj, dBx0,dBx1,dBx2,dBx3), eyj = sel4(jj, dBy0,dBy1,dBy2,dBy3);
        float rx  = __fsub_rn(bxj, axi), ry = __fsub_rn(byj, ayi);
        float den = __fsub_rn(__fmul_rn(dxi, eyj), __fmul_rn(dyi, exj));
        float ad  = fabsf(den);
        float dens = (ad < 1e-9f) ? 1.0f : den;
        float t = __fsub_rn(__fmul_rn(rx, eyj), __fmul_rn(ry, exj)) / dens;
        float u = __fsub_rn(__fmul_rn(rx, dyi), __fmul_rn(ry, dxi)) / dens;
        vl = (ad > 1e-9f) && (t >= -eps) && (t <= ONEPE) && (u >= -eps) && (u <= ONEPE);
        px = __fadd_rn(axi, __fmul_rn(t, dxi));
        py = __fadd_rn(ayi, __fmul_rn(t, dyi));
    }

    unsigned bal = __ballot_sync(FULL, vl) & 0x00FFFFFFu;
    int cnt = __popc(bal);

    float f = vl ? 1.0f : 0.0f;
    float contx = __fmul_rn(px, f);
    float conty = __fmul_rn(py, f);
    float sx = 0.0f, sy = 0.0f;
#pragma unroll
    for (int m = 0; m < 24; m++) {
        float vx = __shfl_sync(FULL, contx, m);
        float vy = __shfl_sync(FULL, conty, m);
        sx = __fadd_rn(sx, vx);
        sy = __fadd_rn(sy, vy);
    }
    int cm = cnt > 1 ? cnt : 1;
    float cenx = sx / (float)cm, ceny = sy / (float)cm;

    int am = bal ? (__ffs(bal) - 1) : 0;
    float anx  = __shfl_sync(FULL, px, am);
    float anyy = __shfl_sync(FULL, py, am);

    float qx = vl ? px : anx;
    float qy = vl ? py : anyy;
    float ang = atan2f(__fsub_rn(qy, ceny), __fsub_rn(qx, cenx));

    int rank = (lane < 24) ? 0 : (100 + lane);
#pragma unroll
    for (int m = 0; m < 24; m++) {
        float am_ = __shfl_sync(FULL, ang, m);
        if (lane < 24 && m != lane) {
            bool less = (am_ < ang) || (am_ == ang && m < lane);
            rank += less ? 1 : 0;
        }
    }

    float X = 0.0f, Y = 0.0f;
#pragma unroll
    for (int m = 0; m < 24; m++) {
        int   rm = __shfl_sync(FULL, rank, m);
        float xm = __shfl_sync(FULL, qx, m);
        float ym = __shfl_sync(FULL, qy, m);
        if (rm == lane) { X = xm; Y = ym; }
    }
    int nxt = (lane == 23) ? 0 : lane + 1;
    float Xn = __shfl_sync(FULL, X, nxt);
    float Yn = __shfl_sync(FULL, Y, nxt);
    float term = __fsub_rn(__fmul_rn(X, Yn), __fmul_rn(Xn, Y));

    float ssum = 0.0f;
#pragma unroll
    for (int m = 0; m < 24; m++) {
        float tv = __shfl_sync(FULL, term, m);
        ssum = __fadd_rn(ssum, tv);
    }
    float area = __fmul_rn(0.5f, fabsf(ssum));
    return (cnt >= 3) ? area : 0.0f;
}

// prep one selected row (rank r, source idx): gather + offset + corners + AABB + class insert
__device__ __forceinline__ void prep_row(int r, int idx, const float* __restrict__ boxes,
                                         const int* __restrict__ labels) {
    float cx = boxes[idx*5+0], cy = boxes[idx*5+1];
    float w  = boxes[idx*5+2], h  = boxes[idx*5+3];
    float a  = boxes[idx*5+4];
    g_bk[r*5+0]=cx; g_bk[r*5+1]=cy; g_bk[r*5+2]=w; g_bk[r*5+3]=h; g_bk[r*5+4]=a;
    int lab = labels[idx];
    g_lab[r] = lab;
    float off = __fmul_rn((float)lab, 10000.0f);
    float cxo = __fadd_rn(cx, off);
    float cyo = __fadd_rn(cy, off);
    g_nms[r*5+0]=cxo; g_nms[r*5+1]=cyo; g_nms[r*5+2]=w; g_nms[r*5+3]=h; g_nms[r*5+4]=a;
    g_area[r] = __fmul_rn(w, h);
    float c = cosf(a), s = sinf(a);
    float dx = __fmul_rn(w, 0.5f), dy = __fmul_rn(h, 0.5f);
    float ox[4] = { dx, -dx, -dx,  dx };
    float oy[4] = { dy,  dy, -dy, -dy };
    float mnx =  3.4e38f, mxx = -3.4e38f, mny = 3.4e38f, mxy = -3.4e38f;
#pragma unroll
    for (int j = 0; j < 4; j++) {
        float x = __fsub_rn(__fadd_rn(cxo, __fmul_rn(ox[j], c)), __fmul_rn(oy[j], s));
        float y = __fadd_rn(__fadd_rn(cyo, __fmul_rn(ox[j], s)), __fmul_rn(oy[j], c));
        g_corn[r*8 + 2*j]     = x;
        g_corn[r*8 + 2*j + 1] = y;
        mnx = fminf(mnx, x); mxx = fmaxf(mxx, x);
        mny = fminf(mny, y); mxy = fmaxf(mxy, y);
    }
    g_aabb[r*4+0]=mnx; g_aabb[r*4+1]=mxx; g_aabb[r*4+2]=mny; g_aabb[r*4+3]=mxy;
    if (lab >= 0 && lab < NCLS) {
        int pos = atomicAdd(&g_clsCnt[lab], 1);
        if (pos < CLSCAP) g_clsIdx[lab*CLSCAP + pos] = r;
    }
}

// ---------------------------------------------------------------- ONE persistent kernel, 2 grid barriers + done-counter
extern __shared__ unsigned char dynbuf[];   // 49152 B

__global__ void __launch_bounds__(NTHR, 1)
k_all(const float* __restrict__ boxes, const float4* __restrict__ sc4,
      const int* __restrict__ labels, float* __restrict__ out, int n4) {
    __shared__ unsigned shSense;
    __shared__ unsigned shC;
    __shared__ int shSkip;
    int tid = threadIdx.x;
    int bid = blockIdx.x;
    if (tid == 0) shSense = 0u;
    __syncthreads();

    // ---------------- P1: default-init + fast compact (s > FAST_T), MLP=8 ----------------
    {
        int gid = bid * NTHR + tid;
        int S   = GRID * NTHR;
        for (int i = gid; i < TOPK; i += S) {
            g_topIdx[i] = -1;
            g_topVal[i] = neginf();
        }
        for (int p = gid; p < n4; p += 8 * S) {
            float4 vv[8];
            int    pp[8];
#pragma unroll
            for (int q = 0; q < 8; q++) {
                pp[q] = p + q * S;
                vv[q] = (pp[q] < n4) ? sc4[pp[q]] : make_float4(0,0,0,0);
            }
#pragma unroll
            for (int q = 0; q < 8; q++) {
                float vs[4] = { vv[q].x, vv[q].y, vv[q].z, vv[q].w };
#pragma unroll
                for (int l = 0; l < 4; l++) {
                    float s = vs[l];
                    if (s > FAST_T) {
                        unsigned pos = atomicAdd(&g_sel[2], 1u);
                        if (pos < CAND_CAP) {
                            unsigned idx = (unsigned)(pp[q] * 4 + l);
                            g_cand[pos] = ((unsigned long long)__float_as_uint(s) << 32) |
                                          (unsigned long long)(0xFFFFFFFFu - idx);
                        }
                    }
                }
            }
        }
    }
    gbar(&shSense);                                            // G1

    // ---------------- skip decision ----------------
    if (tid == 0) {
        unsigned ct = g_sel[2];
        shSkip = (ct >= TOPK && ct <= CAND_CAP) ? 1 : 0;
        shC = ct;
    }
    __syncthreads();
    int skip = shSkip;
    if (!skip) {
        // ---- fallback (correct, barrier-balanced; not hit on this data) ----
        unsigned* h = (unsigned*)dynbuf;
        for (int k = tid; k < NB; k += NTHR) h[k] = 0u;
        __syncthreads();
        for (int p = bid * NTHR + tid; p < n4; p += GRID * NTHR) {
            float4 v = sc4[p];
            float vs[4] = { v.x, v.y, v.z, v.w };
#pragma unroll
            for (int l = 0; l < 4; l++)
                if (vs[l] > 0.05f) atomicAdd(&h[bin_of(__float_as_uint(vs[l]))], 1u);
        }
        __syncthreads();
        for (int k = tid; k < NB; k += NTHR) {
            unsigned v = h[k];
            if (v) atomicAdd(&g_hist1[k], v);
        }
        gbar(&shSense);                                        // Gf1
        if (bid == 0 && tid == 0) {
            unsigned cum = 0; int B1 = -1;
            for (int b = NB - 1; b >= 0; b--) {
                unsigned c = g_hist1[b];
                if (cum + c >= TOPK) { B1 = b; break; }
                cum += c;
            }
            if (B1 < 0) B1 = 0;
            g_sel[0] = (unsigned)B1;
            g_sel[2] = 0u;
        }
        gbar(&shSense);                                        // Gf2
        {
            unsigned B1 = g_sel[0];
            for (int p = bid * NTHR + tid; p < n4; p += GRID * NTHR) {
                float4 v = sc4[p];
                float vs[4] = { v.x, v.y, v.z, v.w };
#pragma unroll
                for (int l = 0; l < 4; l++) {
                    float s = vs[l];
                    if (s > 0.05f) {
                        unsigned fb = __float_as_uint(s);
                        if (bin_of(fb) >= (int)B1) {
                            unsigned pos = atomicAdd(&g_sel[2], 1u);
                            if (pos < CAND_CAP) {
                                unsigned idx = (unsigned)(p * 4 + l);
                                g_cand[pos] = ((unsigned long long)fb << 32) |
                                              (unsigned long long)(0xFFFFFFFFu - idx);
                            }
                        }
                    }
                }
            }
        }
        gbar(&shSense);                                        // Gf3
        if (tid == 0) shC = g_sel[2];
        gbar(&shSense);                                        // Gf4 (pad -> even flips)
        __syncthreads();
    }

    // ---------------- P2: select (16-lane rank) + inline prep ----------------
    {
        unsigned C = shC;
        if (C > CAND_CAP) C = CAND_CAP;
        unsigned long long* sk = (unsigned long long*)dynbuf;  // SELCAP u64
        bool small = (C <= SELCAP);
        const unsigned long long* base;
        if (small) {
            for (unsigned k = (unsigned)tid; k < C; k += NTHR) sk[k] = g_cand[k];
            base = sk;
        } else {
            base = g_cand;
        }
        __syncthreads();
        unsigned lane  = (unsigned)tid & 15u;
        unsigned gidx  = (unsigned)(bid * NTHR + tid) >> 4;
        unsigned cstr  = (unsigned)(GRID * NTHR) >> 4;
        unsigned nIter = (C + cstr - 1) / cstr;                // uniform across grid
        for (unsigned it = 0; it < nIter; it++) {
            unsigned c = gidx + it * cstr;
            bool act = (c < C);
            unsigned long long key = act ? base[c] : 0ULL;
            unsigned rank = 0;
            unsigned k = lane;
            for (; k + 48 < C; k += 64) {
                unsigned long long a0 = base[k], a1 = base[k+16], a2 = base[k+32], a3 = base[k+48];
                rank += (a0 > key) + (a1 > key) + (a2 > key) + (a3 > key);
            }
            for (; k < C; k += 16) rank += (base[k] > key) ? 1u : 0u;
            rank += __shfl_down_sync(0xffffffffu, rank, 8, 16);
            rank += __shfl_down_sync(0xffffffffu, rank, 4, 16);
            rank += __shfl_down_sync(0xffffffffu, rank, 2, 16);
            rank += __shfl_down_sync(0xffffffffu, rank, 1, 16);
            if (act && lane == 0 && rank < TOPK) {
                int idx = (int)(0xFFFFFFFFu - (unsigned)(key & 0xFFFFFFFFull));
                g_topIdx[rank] = idx;
                g_topVal[rank] = __uint_as_float((unsigned)(key >> 32));
                prep_row((int)rank, idx, boxes, labels);       // inline prep
            }
        }
    }
    gbar(&shSense);                                            // G2

    // ---------------- P3: per-class sieve + clip (one block per class) ----------------
    if (bid < NCLS) {
        unsigned* plist = (unsigned*)dynbuf;                   // pair list in SMEM
        __shared__ int pcnt;
        if (tid == 0) pcnt = 0;
        __syncthreads();
        int n = g_clsCnt[bid];
        if (n > CLSCAP) n = CLSCAP;
        if (n >= 2) {
            const int* cl = &g_clsIdx[bid*CLSCAP];
            for (int t = tid; t < n*n; t += NTHR) {
                int i_ = t / n, j_ = t - i_ * n;
                if (i_ >= j_) continue;
                int a = cl[i_], b = cl[j_];
                if (a > b) { int tmp = a; a = b; b = tmp; }
                const float M = 1.0f;
                if (g_aabb[a*4+0] > g_aabb[b*4+1] + M || g_aabb[b*4+0] > g_aabb[a*4+1] + M ||
                    g_aabb[a*4+2] > g_aabb[b*4+3] + M || g_aabb[b*4+2] > g_aabb[a*4+3] + M) continue;
                int pos = atomicAdd(&pcnt, 1);
                if (pos < PAIR_SH) plist[pos] = ((unsigned)a << 16) | (unsigned)b;
            }
        }
        __syncthreads();
        int W = pcnt; if (W > PAIR_SH) W = PAIR_SH;
        int lane = tid & 31;
        int wid  = tid >> 5;
        for (int c = wid; c < W; c += NTHR/32) {
            unsigned e = plist[c];
            int i = (int)(e >> 16), j = (int)(e & 0xFFFFu);
            float inter = warp_inter_area(i, j, lane);
            if (lane == 0) {
                float S   = __fadd_rn(__fsub_rn(__fadd_rn(g_area[i], g_area[j]), inter), 1e-6f);
                float iou = inter / S;
                if (iou > 0.5f) {
                    unsigned pos = atomicAdd(&g_sel[5], 1u);
                    if (pos < SPCAP) g_supPairs[pos] = e;
                }
            }
        }
    }

    // ---------------- half-barrier: blocks signal done and exit; block 0 proceeds ----------------
    __threadfence();
    __syncthreads();
    if (tid == 0) atomicAdd((unsigned*)&g_doneCnt, 1u);
    if (bid != 0) return;
    if (tid == 0) {
        while (g_doneCnt < (unsigned)GRID) __nanosleep(32);
    }
    __syncthreads();
    __threadfence();

    // ---------------- P4: block 0 — slot-compacted NMS + output + self-clean ----------------
    {
        __shared__ unsigned keepW[32];
        __shared__ unsigned raW[32];
        __shared__ unsigned wbase[32];
        __shared__ int lst[DETS];
        __shared__ int kcnt;
        __shared__ int nslots;
        unsigned* mask = (unsigned*)dynbuf;                    // 32KB within dynbuf
        if (tid < 32) { keepW[tid] = 0u; raW[tid] = 0u; }
        __syncthreads();
        for (int i = tid; i < TOPK; i += NTHR)
            if (g_topVal[i] > neginf()) atomicOr(&keepW[i >> 5], 1u << (i & 31));
        unsigned P = g_sel[5];
        if (P > SPCAP) P = SPCAP;
        for (unsigned p = (unsigned)tid; p < P; p += NTHR) {
            unsigned i = g_supPairs[p] >> 16;
            atomicOr(&raW[i >> 5], 1u << (i & 31));
        }
        __syncthreads();
        if (tid < 32) {
            unsigned cnt = __popc(raW[tid]);
            unsigned ex = cnt;
#pragma unroll
            for (int d = 1; d < 32; d <<= 1) {
                unsigned v = __shfl_up_sync(0xffffffffu, ex, d);
                if (tid >= d) ex += v;
            }
            wbase[tid] = ex - cnt;
            if (tid == 31) nslots = (int)ex;
        }
        __syncthreads();
        int NS = nslots;
        if (NS <= MAXSLOTS) {
            for (int k = tid; k < NS * 32; k += NTHR) mask[k] = 0u;
            __syncthreads();
            for (unsigned p = (unsigned)tid; p < P; p += NTHR) {
                unsigned e = g_supPairs[p];
                unsigned i = e >> 16, j = e & 0xFFFFu;
                unsigned w = i >> 5, b = i & 31;
                unsigned slot = wbase[w] + __popc(raW[w] & ((1u << b) - 1u));
                atomicOr(&mask[slot * 32 + (j >> 5)], 1u << (j & 31));
            }
            __syncthreads();
            if (tid < 32) {
                int s = 0;
                for (int w = 0; w < 32; w++) {
                    unsigned rb = raW[w];
                    while (rb) {
                        int b = __ffs(rb) - 1;
                        rb &= rb - 1;
                        bool kept = (keepW[w] >> b) & 1u;
                        if (kept) keepW[tid] &= ~mask[s * 32 + tid];
                        s++;
                        __syncwarp();
                    }
                }
            }
        } else if (tid == 0) {
            for (int w = 0; w < 32; w++) {
                unsigned rb = raW[w];
                while (rb) {
                    int b = __ffs(rb) - 1;
                    rb &= rb - 1;
                    int i = w * 32 + b;
                    if (keepW[w] & (1u << b)) {
                        for (unsigned p = 0; p < P; p++) {
                            unsigned e = g_supPairs[p];
                            if ((int)(e >> 16) == i) {
                                int j = (int)(e & 0xFFFFu);
                                keepW[j >> 5] &= ~(1u << (j & 31));
                            }
                        }
                    }
                }
            }
        }
        __syncthreads();
        if (tid == 0) {
            int p = 0;
            for (int w = 0; w < 32 && p < DETS; w++) {
                unsigned m = keepW[w];
                while (m && p < DETS) {
                    int b = __ffs(m) - 1;
                    m &= m - 1;
                    lst[p++] = w * 32 + b;
                }
            }
            kcnt = p;
        }
        __syncthreads();
        for (int r = tid; r < DETS; r += NTHR) {
            if (r < kcnt) {
                int i = lst[r];
#pragma unroll
                for (int k = 0; k < 5; k++) out[r*5+k] = g_bk[i*5+k];
                out[DETS*5 + r] = (float)g_lab[i];
                out[DETS*6 + r] = g_topVal[i];
            } else {
#pragma unroll
                for (int k = 0; k < 5; k++) out[r*5+k] = 0.0f;
                out[DETS*5 + r] = -1.0f;
                out[DETS*6 + r] = 0.0f;
            }
        }
        // full self-clean for next replay (all other blocks already done)
        for (int k = tid; k < 8; k += NTHR) g_sel[k] = 0u;
        for (int c = tid; c < NCLS; c += NTHR) g_clsCnt[c] = 0;
        if (!skip) for (int k = tid; k < NB; k += NTHR) g_hist1[k] = 0u;
        __syncthreads();
        if (tid == 0) g_doneCnt = 0u;
    }
}

// ---------------------------------------------------------------- launcher: ONE kernel
extern "C" void kernel_launch(void* const* d_in, const int* in_sizes, int n_in,
                              void* d_out, int out_size) {
    const float* boxes  = (const float*)d_in[0];
    const float* scores = (const float*)d_in[1];
    const int*   labels = (const int*)d_in[2];
    int n = in_sizes[1];
    int n4 = n / 4;

    static const int DYN = SELCAP * 8;   // 49152 B
    cudaFuncSetAttribute(k_all, cudaFuncAttributeMaxDynamicSharedMemorySize, DYN);
    k_all<<<GRID, NTHR, DYN>>>(boxes, (const float4*)scores, labels, (float*)d_out, n4);
}

// round 17
// speedup vs baseline: 1.3490x; 1.0073x over previous
#include <cuda_runtime.h>
#include <stdint.h>
#include <math.h>

#define TOPK 1000
#define DETS 300
#define NB    4608          // fallback bins via fb>>13 - BASE
#define BASE  125542        // 0x3D4CCCCD >> 13  (0.05f)
#define CAND_CAP 32768
#define SELCAP   4096
#define NCLS  80
#define CLSCAP 1024
#define PAIR_SH 2048
#define SPCAP 8192
#define MAXSLOTS 256
#define FAST_T 0.999f
#define GRID  132
#define NTHR  512

__device__ unsigned          g_barCount;
__device__ volatile unsigned g_barSense;
__device__ volatile unsigned g_doneCnt;
__device__ unsigned          g_hist1[NB];
__device__ unsigned          g_sel[8];     // [0]=B1 bin  [2]=cand cnt  [5]=sup cnt
__device__ unsigned long long g_cand[CAND_CAP];
__device__ unsigned          g_supPairs[SPCAP];
__device__ int               g_topIdx[TOPK];
__device__ float             g_topVal[TOPK];
__device__ float             g_bk[TOPK*5];
__device__ float             g_nms[TOPK*5];
__device__ float             g_corn[TOPK*8];
__device__ float             g_aabb[TOPK*4];
__device__ float             g_area[TOPK];
__device__ int               g_clsCnt[NCLS];
__device__ int               g_clsIdx[NCLS*CLSCAP];
__device__ int               g_lab[TOPK];

__device__ __forceinline__ float neginf() { return __int_as_float(0xff800000); }

__device__ __forceinline__ int bin_of(unsigned fb) {
    int b = (int)(fb >> 13) - BASE;
    if (b < 0) b = 0;
    if (b > NB - 1) b = NB - 1;
    return b;
}

__device__ __forceinline__ float sel4(int i, float a, float b, float c, float d) {
    return (i == 0) ? a : (i == 1) ? b : (i == 2) ? c : d;
}

// sense-reversing software grid barrier, tight poll (all blocks co-resident: GRID <= #SM)
__device__ __forceinline__ void gbar(unsigned* shSense) {
    __syncthreads();
    if (threadIdx.x == 0) {
        unsigned s = *shSense ^ 1u;
        *shSense = s;
        __threadfence();
        unsigned arrived = atomicAdd(&g_barCount, 1u) + 1u;
        if (arrived == (unsigned)gridDim.x) {
            atomicExch(&g_barCount, 0u);
            __threadfence();
            g_barSense = s;
        } else {
            while (g_barSense != s) { }
        }
        __threadfence();
    }
    __syncthreads();
}

// ---------------------------------------------------------------- warp-cooperative exact clip (bitwise == scalar reference replica)
__device__ __forceinline__ float warp_inter_area(int bi, int bj, int lane) {
    const unsigned FULL = 0xffffffffu;
    const float eps = 1e-6f;
    const float ONEPE = 1.000001f;
    const float* A  = &g_nms[bi*5];
    const float* B  = &g_nms[bj*5];
    const float* cA = &g_corn[bi*8];
    const float* cB = &g_corn[bj*8];
    float ax0=cA[0], ay0=cA[1], ax1=cA[2], ay1=cA[3], ax2=cA[4], ay2=cA[5], ax3=cA[6], ay3=cA[7];
    float bx0=cB[0], by0=cB[1], bx1=cB[2], by1=cB[3], bx2=cB[4], by2=cB[5], bx3=cB[6], by3=cB[7];
    float Acx=A[0], Acy=A[1], Aw=A[2], Ah=A[3], Aa=A[4];
    float Bcx=B[0], Bcy=B[1], Bw=B[2], Bh=B[3], Ba=B[4];

    float dAx0=__fsub_rn(ax1,ax0), dAy0=__fsub_rn(ay1,ay0);
    float dAx1=__fsub_rn(ax2,ax1), dAy1=__fsub_rn(ay2,ay1);
    float dAx2=__fsub_rn(ax3,ax2), dAy2=__fsub_rn(ay3,ay2);
    float dAx3=__fsub_rn(ax0,ax3), dAy3=__fsub_rn(ay0,ay3);
    float dBx0=__fsub_rn(bx1,bx0), dBy0=__fsub_rn(by1,by0);
    float dBx1=__fsub_rn(bx2,bx1), dBy1=__fsub_rn(by2,by1);
    float dBx2=__fsub_rn(bx3,bx2), dBy2=__fsub_rn(by3,by2);
    float dBx3=__fsub_rn(bx0,bx3), dBy3=__fsub_rn(by0,by3);

    float px = 0.0f, py = 0.0f;
    bool  vl = false;
    if (lane < 8) {
        int  c4  = lane & 3;
        bool isA = lane < 4;
        float ptx = isA ? sel4(c4, ax0,ax1,ax2,ax3) : sel4(c4, bx0,bx1,bx2,bx3);
        float pty = isA ? sel4(c4, ay0,ay1,ay2,ay3) : sel4(c4, by0,by1,by2,by3);
        float tcx = isA ? Bcx : Acx;
        float tcy = isA ? Bcy : Acy;
        float tw  = isA ? Bw  : Aw;
        float th  = isA ? Bh  : Ah;
        float ta  = isA ? Ba  : Aa;
        float cc = cosf(ta), ss = sinf(ta);
        float rx = __fsub_rn(ptx, tcx), ry = __fsub_rn(pty, tcy);
        float xr = __fadd_rn(__fmul_rn(rx, cc), __fmul_rn(ry, ss));
        float yr = __fadd_rn(__fmul_rn(-rx, ss), __fmul_rn(ry, cc));
        float lw = __fadd_rn(__fmul_rn(tw, 0.5f), eps);
        float lh = __fadd_rn(__fmul_rn(th, 0.5f), eps);
        vl = (fabsf(xr) <= lw) && (fabsf(yr) <= lh);
        px = ptx; py = pty;
    } else if (lane < 24) {
        int ii = (lane - 8) >> 2, jj = (lane - 8) & 3;
        float axi = sel4(ii, ax0,ax1,ax2,ax3), ayi = sel4(ii, ay0,ay1,ay2,ay3);
        float dxi = sel4(ii, dAx0,dAx1,dAx2,dAx3), dyi = sel4(ii, dAy0,dAy1,dAy2,dAy3);
        float bxj = sel4(jj, bx0,bx1,bx2,bx3), byj = sel4(jj, by0,by1,by2,by3);
        float exj = sel4(jj, dBx0,dBx1,dBx2,dBx3), eyj = sel4(jj, dBy0,dBy1,dBy2,dBy3);
        float rx  = __fsub_rn(bxj, axi), ry = __fsub_rn(byj, ayi);
        float den = __fsub_rn(__fmul_rn(dxi, eyj), __fmul_rn(dyi, exj));
        float ad  = fabsf(den);
        float dens = (ad < 1e-9f) ? 1.0f : den;
        float t = __fsub_rn(__fmul_rn(rx, eyj), __fmul_rn(ry, exj)) / dens;
        float u = __fsub_rn(__fmul_rn(rx, dyi), __fmul_rn(ry, dxi)) / dens;
        vl = (ad > 1e-9f) && (t >= -eps) && (t <= ONEPE) && (u >= -eps) && (u <= ONEPE);
        px = __fadd_rn(axi, __fmul_rn(t, dxi));
        py = __fadd_rn(ayi, __fmul_rn(t, dyi));
    }

    unsigned bal = __ballot_sync(FULL, vl) & 0x00FFFFFFu;
    int cnt = __popc(bal);

    float f = vl ? 1.0f : 0.0f;
    float contx = __fmul_rn(px, f);
    float conty = __fmul_rn(py, f);
    float sx = 0.0f, sy = 0.0f;
#pragma unroll
    for (int m = 0; m < 24; m++) {
        float vx = __shfl_sync(FULL, contx, m);
        float vy = __shfl_sync(FULL, conty, m);
        sx = __fadd_rn(sx, vx);
        sy = __fadd_rn(sy, vy);
    }
    int cm = cnt > 1 ? cnt : 1;
    float cenx = sx / (float)cm, ceny = sy / (float)cm;

    int am = bal ? (__ffs(bal) - 1) : 0;
    float anx  = __shfl_sync(FULL, px, am);
    float anyy = __shfl_sync(FULL, py, am);

    float qx = vl ? px : anx;
    float qy = vl ? py : anyy;
    float ang = atan2f(__fsub_rn(qy, ceny), __fsub_rn(qx, cenx));

    int rank = (lane < 24) ? 0 : (100 + lane);
#pragma unroll
    for (int m = 0; m < 24; m++) {
        float am_ = __shfl_sync(FULL, ang, m);
        if (lane < 24 && m != lane) {
            bool less = (am_ < ang) || (am_ == ang && m < lane);
            rank += less ? 1 : 0;
        }
    }

    float X = 0.0f, Y = 0.0f;
#pragma unroll
    for (int m = 0; m < 24; m++) {
        int   rm = __shfl_sync(FULL, rank, m);
        float xm = __shfl_sync(FULL, qx, m);
        float ym = __shfl_sync(FULL, qy, m);
        if (rm == lane) { X = xm; Y = ym; }
    }
    int nxt = (lane == 23) ? 0 : lane + 1;
    float Xn = __shfl_sync(FULL, X, nxt);
    float Yn = __shfl_sync(FULL, Y, nxt);
    float term = __fsub_rn(__fmul_rn(X, Yn), __fmul_rn(Xn, Y));

    float ssum = 0.0f;
#pragma unroll
    for (int m = 0; m < 24; m++) {
        float tv = __shfl_sync(FULL, term, m);
        ssum = __fadd_rn(ssum, tv);
    }
    float area = __fmul_rn(0.5f, fabsf(ssum));
    return (cnt >= 3) ? area : 0.0f;
}

// prep one selected row (rank r, source idx): gather + offset + corners + AABB + class insert
__device__ __forceinline__ void prep_row(int r, int idx, const float* __restrict__ boxes,
                                         const int* __restrict__ labels) {
    float cx = boxes[idx*5+0], cy = boxes[idx*5+1];
    float w  = boxes[idx*5+2], h  = boxes[idx*5+3];
    float a  = boxes[idx*5+4];
    g_bk[r*5+0]=cx; g_bk[r*5+1]=cy; g_bk[r*5+2]=w; g_bk[r*5+3]=h; g_bk[r*5+4]=a;
    int lab = labels[idx];
    g_lab[r] = lab;
    float off = __fmul_rn((float)lab, 10000.0f);
    float cxo = __fadd_rn(cx, off);
    float cyo = __fadd_rn(cy, off);
    g_nms[r*5+0]=cxo; g_nms[r*5+1]=cyo; g_nms[r*5+2]=w; g_nms[r*5+3]=h; g_nms[r*5+4]=a;
    g_area[r] = __fmul_rn(w, h);
    float c = cosf(a), s = sinf(a);
    float dx = __fmul_rn(w, 0.5f), dy = __fmul_rn(h, 0.5f);
    float ox[4] = { dx, -dx, -dx,  dx };
    float oy[4] = { dy,  dy, -dy, -dy };
    float mnx =  3.4e38f, mxx = -3.4e38f, mny = 3.4e38f, mxy = -3.4e38f;
#pragma unroll
    for (int j = 0; j < 4; j++) {
        float x = __fsub_rn(__fadd_rn(cxo, __fmul_rn(ox[j], c)), __fmul_rn(oy[j], s));
        float y = __fadd_rn(__fadd_rn(cyo, __fmul_rn(ox[j], s)), __fmul_rn(oy[j], c));
        g_corn[r*8 + 2*j]     = x;
        g_corn[r*8 + 2*j + 1] = y;
        mnx = fminf(mnx, x); mxx = fmaxf(mxx, x);
        mny = fminf(mny, y); mxy = fmaxf(mxy, y);
    }
    g_aabb[r*4+0]=mnx; g_aabb[r*4+1]=mxx; g_aabb[r*4+2]=mny; g_aabb[r*4+3]=mxy;
    if (lab >= 0 && lab < NCLS) {
        int pos = atomicAdd(&g_clsCnt[lab], 1);
        if (pos < CLSCAP) g_clsIdx[lab*CLSCAP + pos] = r;
    }
}

// ---------------------------------------------------------------- ONE persistent kernel, 2 grid barriers + done-counter
extern __shared__ unsigned char dynbuf[];   // 32768 B

__global__ void __launch_bounds__(NTHR, 1)
k_all(const float* __restrict__ boxes, const float4* __restrict__ sc4,
      const int* __restrict__ labels, float* __restrict__ out, int n4) {
    __shared__ unsigned shSense;
    __shared__ unsigned shC;
    __shared__ int shSkip;
    int tid = threadIdx.x;
    int bid = blockIdx.x;
    if (tid == 0) shSense = 0u;
    __syncthreads();

    // ---------------- P1: default-init + fast compact (s > FAST_T), MLP=8, warp-aggregated ----------------
    {
        int gid = bid * NTHR + tid;
        int S   = GRID * NTHR;
        int lane = tid & 31;
        for (int i = gid; i < TOPK; i += S) {
            g_topIdx[i] = -1;
            g_topVal[i] = neginf();
        }
        for (int p = gid; p < n4; p += 8 * S) {
            float4 vv[8];
            int    pp[8];
#pragma unroll
            for (int q = 0; q < 8; q++) {
                pp[q] = p + q * S;
                vv[q] = (pp[q] < n4) ? sc4[pp[q]] : make_float4(0,0,0,0);
            }
#pragma unroll
            for (int q = 0; q < 8; q++) {
                float vs[4] = { vv[q].x, vv[q].y, vv[q].z, vv[q].w };
#pragma unroll
                for (int l = 0; l < 4; l++) {
                    float s = vs[l];
                    bool hit = (s > FAST_T);
                    unsigned bal = __ballot_sync(0xffffffffu, hit);
                    if (bal) {
                        unsigned nb = __popc(bal);
                        unsigned base;
                        if (lane == __ffs(bal) - 1) base = atomicAdd(&g_sel[2], nb);
                        base = __shfl_sync(0xffffffffu, base, __ffs(bal) - 1);
                        if (hit) {
                            unsigned pos = base + __popc(bal & ((1u << lane) - 1u));
                            if (pos < CAND_CAP) {
                                unsigned idx = (unsigned)(pp[q] * 4 + l);
                                g_cand[pos] = ((unsigned long long)__float_as_uint(s) << 32) |
                                              (unsigned long long)(0xFFFFFFFFu - idx);
                            }
                        }
                    }
                }
            }
        }
    }
    gbar(&shSense);                                            // G1

    // ---------------- skip decision ----------------
    if (tid == 0) {
        unsigned ct = g_sel[2];
        shSkip = (ct >= TOPK && ct <= CAND_CAP) ? 1 : 0;
        shC = ct;
    }
    __syncthreads();
    int skip = shSkip;
    if (!skip) {
        // ---- fallback (correct, barrier-balanced; not hit on this data) ----
        unsigned* h = (unsigned*)dynbuf;
        for (int k = tid; k < NB; k += NTHR) h[k] = 0u;
        __syncthreads();
        for (int p = bid * NTHR + tid; p < n4; p += GRID * NTHR) {
            float4 v = sc4[p];
            float vs[4] = { v.x, v.y, v.z, v.w };
#pragma unroll
            for (int l = 0; l < 4; l++)
                if (vs[l] > 0.05f) atomicAdd(&h[bin_of(__float_as_uint(vs[l]))], 1u);
        }
        __syncthreads();
        for (int k = tid; k < NB; k += NTHR) {
            unsigned v = h[k];
            if (v) atomicAdd(&g_hist1[k], v);
        }
        gbar(&shSense);                                        // Gf1
        if (bid == 0 && tid == 0) {
            unsigned cum = 0; int B1 = -1;
            for (int b = NB - 1; b >= 0; b--) {
                unsigned c = g_hist1[b];
                if (cum + c >= TOPK) { B1 = b; break; }
                cum += c;
            }
            if (B1 < 0) B1 = 0;
            g_sel[0] = (unsigned)B1;
            g_sel[2] = 0u;
        }
        gbar(&shSense);                                        // Gf2
        {
            unsigned B1 = g_sel[0];
            for (int p = bid * NTHR + tid; p < n4; p += GRID * NTHR) {
                float4 v = sc4[p];
                float vs[4] = { v.x, v.y, v.z, v.w };
#pragma unroll
                for (int l = 0; l < 4; l++) {
                    float s = vs[l];
                    if (s > 0.05f) {
                        unsigned fb = __float_as_uint(s);
                        if (bin_of(fb) >= (int)B1) {
                            unsigned pos = atomicAdd(&g_sel[2], 1u);
                            if (pos < CAND_CAP) {
                                unsigned idx = (unsigned)(p * 4 + l);
                                g_cand[pos] = ((unsigned long long)fb << 32) |
                                              (unsigned long long)(0xFFFFFFFFu - idx);
                            }
                        }
                    }
                }
            }
        }
        gbar(&shSense);                                        // Gf3
        if (tid == 0) shC = g_sel[2];
        gbar(&shSense);                                        // Gf4 (pad -> even flips)
        __syncthreads();
    }

    // ---------------- P2: select (16-lane rank) + inline prep ----------------
    {
        unsigned C = shC;
        if (C > CAND_CAP) C = CAND_CAP;
        unsigned long long* sk = (unsigned long long*)dynbuf;  // SELCAP u64 = 32KB
        bool small = (C <= SELCAP);
        const unsigned long long* base;
        if (small) {
            for (unsigned k = (unsigned)tid; k < C; k += NTHR) sk[k] = g_cand[k];
            base = sk;
        } else {
            base = g_cand;
        }
        __syncthreads();
        unsigned lane  = (unsigned)tid & 15u;
        unsigned gidx  = (unsigned)(bid * NTHR + tid) >> 4;
        unsigned cstr  = (unsigned)(GRID * NTHR) >> 4;
        unsigned nIter = (C + cstr - 1) / cstr;                // uniform across grid
        for (unsigned it = 0; it < nIter; it++) {
            unsigned c = gidx + it * cstr;
            bool act = (c < C);
            unsigned long long key = act ? base[c] : 0ULL;
            unsigned rank = 0;
            unsigned k = lane;
            for (; k + 48 < C; k += 64) {
                unsigned long long a0 = base[k], a1 = base[k+16], a2 = base[k+32], a3 = base[k+48];
                rank += (a0 > key) + (a1 > key) + (a2 > key) + (a3 > key);
            }
            for (; k < C; k += 16) rank += (base[k] > key) ? 1u : 0u;
            rank += __shfl_down_sync(0xffffffffu, rank, 8, 16);
            rank += __shfl_down_sync(0xffffffffu, rank, 4, 16);
            rank += __shfl_down_sync(0xffffffffu, rank, 2, 16);
            rank += __shfl_down_sync(0xffffffffu, rank, 1, 16);
            if (act && lane == 0 && rank < TOPK) {
                int idx = (int)(0xFFFFFFFFu - (unsigned)(key & 0xFFFFFFFFull));
                g_topIdx[rank] = idx;
                g_topVal[rank] = __uint_as_float((unsigned)(key >> 32));
                prep_row((int)rank, idx, boxes, labels);       // inline prep
            }
        }
    }
    gbar(&shSense);                                            // G2

    // ---------------- P3: per-class sieve + clip (one block per class) ----------------
    if (bid < NCLS) {
        unsigned* plist = (unsigned*)dynbuf;                   // pair list in SMEM
        __shared__ int pcnt;
        if (tid == 0) pcnt = 0;
        __syncthreads();
        int n = g_clsCnt[bid];
        if (n > CLSCAP) n = CLSCAP;
        if (n >= 2) {
            const int* cl = &g_clsIdx[bid*CLSCAP];
            for (int t = tid; t < n*n; t += NTHR) {
                int i_ = t / n, j_ = t - i_ * n;
                if (i_ >= j_) continue;
                int a = cl[i_], b = cl[j_];
                if (a > b) { int tmp = a; a = b; b = tmp; }
                const float M = 1.0f;
                if (g_aabb[a*4+0] > g_aabb[b*4+1] + M || g_aabb[b*4+0] > g_aabb[a*4+1] + M ||
                    g_aabb[a*4+2] > g_aabb[b*4+3] + M || g_aabb[b*4+2] > g_aabb[a*4+3] + M) continue;
                int pos = atomicAdd(&pcnt, 1);
                if (pos < PAIR_SH) plist[pos] = ((unsigned)a << 16) | (unsigned)b;
            }
        }
        __syncthreads();
        int W = pcnt; if (W > PAIR_SH) W = PAIR_SH;
        int lane = tid & 31;
        int wid  = tid >> 5;
        for (int c = wid; c < W; c += NTHR/32) {
            unsigned e = plist[c];
            int i = (int)(e >> 16), j = (int)(e & 0xFFFFu);
            float inter = warp_inter_area(i, j, lane);
            if (lane == 0) {
                float S   = __fadd_rn(__fsub_rn(__fadd_rn(g_area[i], g_area[j]), inter), 1e-6f);
                float iou = inter / S;
                if (iou > 0.5f) {
                    unsigned pos = atomicAdd(&g_sel[5], 1u);
                    if (pos < SPCAP) g_supPairs[pos] = e;
                }
            }
        }
    }

    // ---------------- half-barrier: blocks signal done and exit; block 0 proceeds ----------------
    __threadfence();
    __syncthreads();
    if (tid == 0) atomicAdd((unsigned*)&g_doneCnt, 1u);
    if (bid != 0) return;
    if (tid == 0) {
        while (g_doneCnt < (unsigned)GRID) { }
    }
    __syncthreads();
    __threadfence();

    // ---------------- P4: block 0 — slot-compacted NMS + output + self-clean ----------------
    {
        __shared__ unsigned keepW[32];
        __shared__ unsigned raW[32];
        __shared__ unsigned wbase[32];
        __shared__ int lst[DETS];
        __shared__ int kcnt;
        __shared__ int nslots;
        unsigned* mask = (unsigned*)dynbuf;                    // 32KB within dynbuf
        if (tid < 32) { keepW[tid] = 0u; raW[tid] = 0u; }
        __syncthreads();
        for (int i = tid; i < TOPK; i += NTHR)
            if (g_topVal[i] > neginf()) atomicOr(&keepW[i >> 5], 1u << (i & 31));
        unsigned P = g_sel[5];
        if (P > SPCAP) P = SPCAP;
        for (unsigned p = (unsigned)tid; p < P; p += NTHR) {
            unsigned i = g_supPairs[p] >> 16;
            atomicOr(&raW[i >> 5], 1u << (i & 31));
        }
        __syncthreads();
        if (tid < 32) {
            unsigned cnt = __popc(raW[tid]);
            unsigned ex = cnt;
#pragma unroll
            for (int d = 1; d < 32; d <<= 1) {
                unsigned v = __shfl_up_sync(0xffffffffu, ex, d);
                if (tid >= d) ex += v;
            }
            wbase[tid] = ex - cnt;
            if (tid == 31) nslots = (int)ex;
        }
        __syncthreads();
        int NS = nslots;
        if (NS <= MAXSLOTS) {
            for (int k = tid; k < NS * 32; k += NTHR) mask[k] = 0u;
            __syncthreads();
            for (unsigned p = (unsigned)tid; p < P; p += NTHR) {
                unsigned e = g_supPairs[p];
                unsigned i = e >> 16, j = e & 0xFFFFu;
                unsigned w = i >> 5, b = i & 31;
                unsigned slot = wbase[w] + __popc(raW[w] & ((1u << b) - 1u));
                atomicOr(&mask[slot * 32 + (j >> 5)], 1u << (j & 31));
            }
            __syncthreads();
            if (tid < 32) {
                int s = 0;
                for (int w = 0; w < 32; w++) {
                    unsigned rb = raW[w];
                    while (rb) {
                        int b = __ffs(rb) - 1;
                        rb &= rb - 1;
                        bool kept = (keepW[w] >> b) & 1u;
                        if (kept) keepW[tid] &= ~mask[s * 32 + tid];
                        s++;
                        __syncwarp();
                    }
                }
            }
        } else if (tid == 0) {
            for (int w = 0; w < 32; w++) {
                unsigned rb = raW[w];
                while (rb) {
                    int b = __ffs(rb) - 1;
                    rb &= rb - 1;
                    int i = w * 32 + b;
                    if (keepW[w] & (1u << b)) {
                        for (unsigned p = 0; p < P; p++) {
                            unsigned e = g_supPairs[p];
                            if ((int)(e >> 16) == i) {
                                int j = (int)(e & 0xFFFFu);
                                keepW[j >> 5] &= ~(1u << (j & 31));
                            }
                        }
                    }
                }
            }
        }
        __syncthreads();
        if (tid == 0) {
            int p = 0;
            for (int w = 0; w < 32 && p < DETS; w++) {
                unsigned m = keepW[w];
                while (m && p < DETS) {
                    int b = __ffs(m) - 1;
                    m &= m - 1;
                    lst[p++] = w * 32 + b;
                }
            }
            kcnt = p;
        }
        __syncthreads();
        for (int r = tid; r < DETS; r += NTHR) {
            if (r < kcnt) {
                int i = lst[r];
#pragma unroll
                for (int k = 0; k < 5; k++) out[r*5+k] = g_bk[i*5+k];
                out[DETS*5 + r] = (float)g_lab[i];
                out[DETS*6 + r] = g_topVal[i];
            } else {
#pragma unroll
                for (int k = 0; k < 5; k++) out[r*5+k] = 0.0f;
                out[DETS*5 + r] = -1.0f;
                out[DETS*6 + r] = 0.0f;
            }
        }
        // full self-clean for next replay (all other blocks already done)
        for (int k = tid; k < 8; k += NTHR) g_sel[k] = 0u;
        for (int c = tid; c < NCLS; c += NTHR) g_clsCnt[c] = 0;
        if (!skip) for (int k = tid; k < NB; k += NTHR) g_hist1[k] = 0u;
        __syncthreads();
        if (tid == 0) g_doneCnt = 0u;
    }
}

// ---------------------------------------------------------------- launcher: ONE kernel
extern "C" void kernel_launch(void* const* d_in, const int* in_sizes, int n_in,
                              void* d_out, int out_size) {
    const float* boxes  = (const float*)d_in[0];
    const float* scores = (const float*)d_in[1];
    const int*   labels = (const int*)d_in[2];
    int n = in_sizes[1];
    int n4 = n / 4;

    static const int DYN = SELCAP * 8;   // 32768 B
    cudaFuncSetAttribute(k_all, cudaFuncAttributeMaxDynamicSharedMemorySize, DYN);
    k_all<<<GRID, NTHR, DYN>>>(boxes, (const float4*)scores, labels, (float*)d_out, n4);
}